// round 13
// baseline (speedup 1.0000x reference)
#include <cuda_runtime.h>
#include <cuda_fp16.h>
#include <cstdint>

#define TOK 8192
#define SEQ 1024
#define DM  768
#define NH  12
#define DH  64
#define DMLP 3072

// ---------------- scratch ----------------------------------------------------
__device__ __half g_n1h[TOK*DM];
__device__ __half g_q [TOK*DM];
__device__ __half g_k [TOK*DM];
__device__ __half g_v [TOK*DM];
__device__ __half g_zh[TOK*DM];
__device__ float  g_rm[TOK*DM];
__device__ __half g_n2h[TOK*DM];
__device__ __half g_hh[TOK*DMLP];
__device__ __half g_WqkvT[3*DM*DM];
__device__ __half g_WoT  [DM*DM];
__device__ __half g_WinT [DMLP*DM];
__device__ __half g_WoutT[DM*DMLP];
__device__ float  g_qkvb[3*DM];

typedef unsigned long long u64;

__device__ __forceinline__ float gelu_new(float x) {
    float x3 = x * x * x;
    float t  = tanhf(0.7978845608028654f * (x + 0.044715f * x3));
    return 0.5f * x * (1.0f + t);
}

// ---------------- mma / ldmatrix / cp.async helpers ----------------------------
__device__ __forceinline__ uint32_t smem_u32(const void* p) {
    uint32_t a;
    asm("{ .reg .u64 t; cvta.to.shared.u64 t, %1; cvt.u32.u64 %0, t; }" : "=r"(a) : "l"(p));
    return a;
}
__device__ __forceinline__ void cpasync16(uint32_t dst, const void* src) {
    asm volatile("cp.async.cg.shared.global [%0], [%1], 16;" :: "r"(dst), "l"(src));
}
#define CP_COMMIT() asm volatile("cp.async.commit_group;" ::: "memory")
#define CP_WAIT1()  asm volatile("cp.async.wait_group 1;" ::: "memory")
#define CP_WAIT0()  asm volatile("cp.async.wait_group 0;" ::: "memory")

__device__ __forceinline__ void ldsm4(uint32_t &r0, uint32_t &r1, uint32_t &r2, uint32_t &r3,
                                      uint32_t addr) {
    asm volatile("ldmatrix.sync.aligned.m8n8.x4.shared.b16 {%0,%1,%2,%3}, [%4];"
                 : "=r"(r0), "=r"(r1), "=r"(r2), "=r"(r3) : "r"(addr));
}
__device__ __forceinline__ void ldsm4t(uint32_t &r0, uint32_t &r1, uint32_t &r2, uint32_t &r3,
                                       uint32_t addr) {
    asm volatile("ldmatrix.sync.aligned.m8n8.x4.trans.shared.b16 {%0,%1,%2,%3}, [%4];"
                 : "=r"(r0), "=r"(r1), "=r"(r2), "=r"(r3) : "r"(addr));
}
__device__ __forceinline__ void mma16816(float* c, uint32_t a0, uint32_t a1, uint32_t a2,
                                         uint32_t a3, uint32_t b0, uint32_t b1) {
    asm volatile("mma.sync.aligned.m16n8k16.row.col.f32.f16.f16.f32 "
                 "{%0,%1,%2,%3},{%4,%5,%6,%7},{%8,%9},{%0,%1,%2,%3};"
                 : "+f"(c[0]), "+f"(c[1]), "+f"(c[2]), "+f"(c[3])
                 : "r"(a0), "r"(a1), "r"(a2), "r"(a3), "r"(b0), "r"(b1));
}
__device__ __forceinline__ uint32_t exp2_h2(float e0, float e1) {
    __half2 h = __floats2half2_rn(e0, e1);
    uint32_t hi = *(uint32_t*)&h, r;
    asm("ex2.approx.f16x2 %0, %1;" : "=r"(r) : "r"(hi));
    return r;
}
__device__ __forceinline__ float exp2_poly(float t) {
    t = fmaxf(t, -30.0f);
    const float z = t + 12582912.0f;
    const int   n = __float_as_int(z) << 23;
    const float f = t - (z - 12582912.0f);
    float p = 0.009618129f;
    p = fmaf(p, f, 0.05550411f);
    p = fmaf(p, f, 0.24022651f);
    p = fmaf(p, f, 0.69314718f);
    p = fmaf(p, f, 1.0f);
    return __int_as_float(__float_as_int(p) + n);
}

// ---------------- HMMA GEMM: BK=64, 3 stages, 4 warps, warp tile 64x64 ----------
#define LDSH 72
#define STG_H (2 * 128 * LDSH)
#define GEMM_SMEM (3 * STG_H * 2)        // 110592 B

template<int EPI>
__global__ void __launch_bounds__(128, 2) mma_gemm(
    const __half* __restrict__ A, const __half* __restrict__ Bt,
    const float* __restrict__ bias, const float* __restrict__ R,
    float* __restrict__ C, __half* __restrict__ Ch,
    __half* __restrict__ Qp, __half* __restrict__ Kp, __half* __restrict__ Vp,
    int N, int K)
{
    extern __shared__ __half sm[];
    const int tid  = threadIdx.x;
    const int lane = tid & 31, wid = tid >> 5;    // 4 warps
    const int wm = wid >> 1, wn = wid & 1;        // 2 x 2 grid, 64x64 tiles
    const int col0 = blockIdx.x * 128;
    const int row0 = blockIdx.y * 128;
    const int KT = K / 64;

    const uint32_t sbase = smem_u32(sm);

    float acc[4][8][4];
    #pragma unroll
    for (int i = 0; i < 4; i++)
        #pragma unroll
        for (int j = 0; j < 8; j++)
            #pragma unroll
            for (int x = 0; x < 4; x++) acc[i][j][x] = 0.0f;

    auto load_stage = [&](int s, int kt) {
        const uint32_t st = sbase + (uint32_t)s * (STG_H * 2);
        const int kk = kt * 64;
        #pragma unroll
        for (int h = 0; h < 8; h++) {
            const int c  = tid + h * 128;       // 0..1023
            const int r  = c >> 3;              // 0..127
            const int kc = (c & 7) * 8;
            cpasync16(st + (uint32_t)(r * LDSH + kc) * 2,
                      A + (size_t)(row0 + r) * K + kk + kc);
            cpasync16(st + (uint32_t)((128 + r) * LDSH + kc) * 2,
                      Bt + (size_t)(col0 + r) * K + kk + kc);
        }
    };

    auto compute_stage = [&](int s) {
        const uint32_t aB = sbase + (uint32_t)s * (STG_H * 2);
        const uint32_t bB = aB + 128 * LDSH * 2;
        const int lrow = lane & 15;
        const int lcol = (lane >> 4) * 8;
        #pragma unroll
        for (int ks = 0; ks < 4; ks++) {
            const int ko = ks * 16 + lcol;
            uint32_t af[4][4];
            #pragma unroll
            for (int i = 0; i < 4; i++) {
                const int row = wm * 64 + i * 16 + lrow;
                ldsm4(af[i][0], af[i][1], af[i][2], af[i][3],
                      aB + (uint32_t)(row * LDSH + ko) * 2);
            }
            #pragma unroll
            for (int j2 = 0; j2 < 4; j2++) {
                uint32_t b0, b1, b2, b3;
                const int row = wn * 64 + j2 * 16 + lrow;
                ldsm4(b0, b1, b2, b3, bB + (uint32_t)(row * LDSH + ko) * 2);
                #pragma unroll
                for (int i = 0; i < 4; i++) {
                    mma16816(acc[i][2 * j2],     af[i][0], af[i][1], af[i][2], af[i][3], b0, b2);
                    mma16816(acc[i][2 * j2 + 1], af[i][0], af[i][1], af[i][2], af[i][3], b1, b3);
                }
            }
        }
    };

    load_stage(0, 0); CP_COMMIT();
    load_stage(1, 1); CP_COMMIT();

    int sidx = 0;
    for (int kt = 0; kt < KT; kt++) {
        CP_WAIT1();
        __syncthreads();
        if (kt + 2 < KT) {
            int ns = sidx + 2; if (ns >= 3) ns -= 3;
            load_stage(ns, kt + 2);
        }
        CP_COMMIT();
        compute_stage(sidx);
        if (++sidx == 3) sidx = 0;
    }

    const int g = lane >> 2, t4 = lane & 3;
    #pragma unroll
    for (int i = 0; i < 4; i++) {
        const int r0g = row0 + wm * 64 + i * 16 + g;
        #pragma unroll
        for (int j = 0; j < 8; j++) {
            const int c0g = col0 + wn * 64 + j * 8 + t4 * 2;
            const float b0 = __ldg(&bias[c0g]);
            const float b1 = __ldg(&bias[c0g + 1]);
            float* a = acc[i][j];
            if (EPI == 0) {
                float2 rA = *(const float2*)&R[(size_t)r0g * N + c0g];
                float2 rB = *(const float2*)&R[(size_t)(r0g + 8) * N + c0g];
                *(float2*)&C[(size_t)r0g * N + c0g] =
                    make_float2(a[0] + b0 + rA.x, a[1] + b1 + rA.y);
                *(float2*)&C[(size_t)(r0g + 8) * N + c0g] =
                    make_float2(a[2] + b0 + rB.x, a[3] + b1 + rB.y);
            } else if (EPI == 1) {
                *(__half2*)&Ch[(size_t)r0g * N + c0g] =
                    __floats2half2_rn(gelu_new(a[0] + b0), gelu_new(a[1] + b1));
                *(__half2*)&Ch[(size_t)(r0g + 8) * N + c0g] =
                    __floats2half2_rn(gelu_new(a[2] + b0), gelu_new(a[3] + b1));
            } else {
                const int which = c0g / DM;
                const int h2    = (c0g % DM) >> 6;
                const int e0    = c0g & 63;
                const float sc  = (which == 0) ? 0.125f : 1.0f;
                __half* OP = (which == 0) ? Qp : ((which == 1) ? Kp : Vp);
                __half* p0 = OP + ((size_t)((r0g >> 10) * NH + h2)) * (SEQ * DH)
                               + (size_t)(r0g & (SEQ - 1)) * DH + e0;
                __half* p1 = OP + ((size_t)(((r0g + 8) >> 10) * NH + h2)) * (SEQ * DH)
                               + (size_t)((r0g + 8) & (SEQ - 1)) * DH + e0;
                *(__half2*)p0 = __floats2half2_rn((a[0] + b0) * sc, (a[1] + b1) * sc);
                *(__half2*)p1 = __floats2half2_rn((a[2] + b0) * sc, (a[3] + b1) * sc);
            }
        }
    }
}

// ---------------- merged weight prep (round-10) ---------------------------------
__device__ __forceinline__ void tr_tile(const float* __restrict__ in,
                                        __half* __restrict__ out,
                                        int C, int ldo, int c0, int r0,
                                        float* t)
{
    const int tx = threadIdx.x, ty = threadIdx.y;
    #pragma unroll
    for (int i = 0; i < 32; i += 8)
        t[(ty + i) * 33 + tx] = in[(size_t)(r0 + ty + i) * C + c0 + tx];
    __syncthreads();
    #pragma unroll
    for (int i = 0; i < 32; i += 8)
        out[(size_t)(c0 + ty + i) * ldo + r0 + tx] = __float2half(t[tx * 33 + ty + i]);
}

__global__ void __launch_bounds__(256) prep_all(
    const float* __restrict__ WQ, const float* __restrict__ WK, const float* __restrict__ WV,
    const float* __restrict__ WO, const float* __restrict__ Win, const float* __restrict__ Wout,
    const float* __restrict__ bq, const float* __restrict__ bk, const float* __restrict__ bv,
    __half* __restrict__ WqkvT, __half* __restrict__ WoT,
    __half* __restrict__ WinT,  __half* __restrict__ WoutT,
    float* __restrict__ qkvb)
{
    __shared__ float t[32 * 33];
    const int bid = blockIdx.x;

    if (bid < 1728) {
        const int which = bid / 576;
        const int r = bid % 576;
        const int h = r / 48, u = r % 48;
        const int c0 = (u & 1) * 32, r0 = (u >> 1) * 32;
        const float* in = ((which == 0) ? WQ : (which == 1) ? WK : WV) + (size_t)h * DM * DH;
        __half* out = WqkvT + (size_t)which * DM * DM + (size_t)h * DH * DM;
        tr_tile(in, out, DH, DM, c0, r0, t);
    } else if (bid < 2304) {
        const int r = bid - 1728;
        const int h = r / 48, u = r % 48;
        const int c0 = (u % 24) * 32, r0 = (u / 24) * 32;
        tr_tile(WO + (size_t)h * DH * DM, WoT + h * DH, DM, DM, c0, r0, t);
    } else if (bid < 4608) {
        const int r = bid - 2304;
        const int c0 = (r % 96) * 32, r0 = (r / 96) * 32;
        tr_tile(Win, WinT, DMLP, DM, c0, r0, t);
    } else if (bid < 6912) {
        const int r = bid - 4608;
        const int c0 = (r % 24) * 32, r0 = (r / 24) * 32;
        tr_tile(Wout, WoutT, DM, DMLP, c0, r0, t);
    } else {
        const int n = (bid - 6912) * 256 + threadIdx.y * 32 + threadIdx.x;
        if (n < 3 * DM) {
            const float* s = (n < DM) ? bq : ((n < 2 * DM) ? bk : bv);
            qkvb[n] = s[n % DM];
        }
    }
}

// ---------------- LayerNorm (fp32 in -> fp16 out) ------------------------------
__global__ void __launch_bounds__(256) ln_kernel(
    const float* __restrict__ X, const float* __restrict__ w,
    const float* __restrict__ b, __half* __restrict__ Y)
{
    const int row = blockIdx.x;
    const float* x = X + (size_t)row * DM;
    __half* y = Y + (size_t)row * DM;
    const int t = threadIdx.x;

    float v0 = x[t], v1 = x[t + 256], v2 = x[t + 512];
    float s = v0 + v1 + v2;
    float q = v0 * v0 + v1 * v1 + v2 * v2;

    __shared__ float sh[16];
    #pragma unroll
    for (int o = 16; o > 0; o >>= 1) {
        s += __shfl_xor_sync(0xffffffffu, s, o);
        q += __shfl_xor_sync(0xffffffffu, q, o);
    }
    const int lane = t & 31, wid = t >> 5;
    if (lane == 0) { sh[wid] = s; sh[wid + 8] = q; }
    __syncthreads();
    if (t == 0) {
        float ss = 0.f, qq = 0.f;
        #pragma unroll
        for (int i = 0; i < 8; i++) { ss += sh[i]; qq += sh[i + 8]; }
        sh[0] = ss; sh[8] = qq;
    }
    __syncthreads();
    s = sh[0]; q = sh[8];
    const float mu  = s * (1.0f / DM);
    const float inv = rsqrtf(q * (1.0f / DM) - mu * mu + 1e-5f);

    y[t]       = __float2half((v0 - mu) * inv * w[t]       + b[t]);
    y[t + 256] = __float2half((v1 - mu) * inv * w[t + 256] + b[t + 256]);
    y[t + 512] = __float2half((v2 - mu) * inv * w[t + 512] + b[t + 512]);
}

// ---------------- tensor-core causal flash attention (round-5 best) -------------
#define ALD 72
#define ATTN_SMEM ((64 + 128 + 128) * ALD * 2)
#define L2E 1.4426950408889634f

__global__ void __launch_bounds__(128) attn_mma(
    const __half* __restrict__ Q, const __half* __restrict__ K,
    const __half* __restrict__ V, __half* __restrict__ Z)
{
    extern __shared__ __half as_[];
    __half* Qs = as_;
    __half* Ks = as_ + 64 * ALD;
    __half* Vs = as_ + (64 + 128) * ALD;

    const int tid  = threadIdx.x;
    const int lane = tid & 31;
    const int w    = tid >> 5;
    const int bh   = blockIdx.y;
    const int q0   = (15 - blockIdx.x) * 64;
    const int nt   = q0 / 64 + 1;

    const __half* Qb = Q + (size_t)bh * (SEQ * DH);
    const __half* Kb = K + (size_t)bh * (SEQ * DH);
    const __half* Vb = V + (size_t)bh * (SEQ * DH);

    const uint32_t sQ = smem_u32(Qs);
    const uint32_t sK = smem_u32(Ks);
    const uint32_t sV = smem_u32(Vs);

    #pragma unroll
    for (int i = 0; i < 4; i++) {
        int c = tid + i * 128;
        int row = c >> 3, col = (c & 7) * 8;
        *(float4*)&Qs[row * ALD + col] = *(const float4*)&Qb[(size_t)(q0 + row) * DH + col];
    }

    auto load_kv = [&](int kt, int buf) {
        const int k0 = kt * 64;
        const uint32_t bK_ = sK + (uint32_t)buf * (64 * ALD * 2);
        const uint32_t bV_ = sV + (uint32_t)buf * (64 * ALD * 2);
        #pragma unroll
        for (int i = 0; i < 4; i++) {
            int c = tid + i * 128;
            int row = c >> 3, col = (c & 7) * 8;
            cpasync16(bK_ + (uint32_t)(row * ALD + col) * 2,
                      Kb + (size_t)(k0 + row) * DH + col);
            cpasync16(bV_ + (uint32_t)(row * ALD + col) * 2,
                      Vb + (size_t)(k0 + row) * DH + col);
        }
    };

    load_kv(0, 0); CP_COMMIT();
    __syncthreads();

    uint32_t qf[4][4];
    {
        const uint32_t qoff = sQ + (uint32_t)((w * 16 + (lane & 15)) * ALD + (lane >> 4) * 8) * 2;
        #pragma unroll
        for (int ks = 0; ks < 4; ks++)
            ldsm4(qf[ks][0], qf[ks][1], qf[ks][2], qf[ks][3], qoff + ks * 32);
    }

    float o[8][4];
    #pragma unroll
    for (int j = 0; j < 8; j++)
        #pragma unroll
        for (int x = 0; x < 4; x++) o[j][x] = 0.0f;
    float m0 = -1e30f, m1 = -1e30f, l0 = 0.0f, l1 = 0.0f;

    const uint32_t koff = (uint32_t)(((lane >> 4) * 8 + (lane & 7)) * ALD + ((lane >> 3) & 1) * 8) * 2;
    const uint32_t voff = (uint32_t)(((lane & 7) + ((lane >> 3) & 1) * 8) * ALD + (lane >> 4) * 8) * 2;
    const int grow = lane >> 2, gcol = (lane & 3) * 2;

    for (int kt = 0; kt < nt; kt++) {
        const int buf = kt & 1;
        if (kt + 1 < nt) { load_kv(kt + 1, buf ^ 1); CP_COMMIT(); CP_WAIT1(); }
        else            { CP_WAIT0(); }
        __syncthreads();

        const uint32_t bK_ = sK + (uint32_t)buf * (64 * ALD * 2);
        const uint32_t bV_ = sV + (uint32_t)buf * (64 * ALD * 2);

        float c_[8][4];
        #pragma unroll
        for (int j = 0; j < 8; j++)
            #pragma unroll
            for (int x = 0; x < 4; x++) c_[j][x] = 0.0f;
        #pragma unroll
        for (int ks = 0; ks < 4; ks++) {
            #pragma unroll
            for (int j2 = 0; j2 < 4; j2++) {
                uint32_t b0, b1, b2, b3;
                ldsm4(b0, b1, b2, b3, bK_ + koff + (uint32_t)(j2 * 16 * ALD + ks * 16) * 2);
                mma16816(c_[2 * j2],     qf[ks][0], qf[ks][1], qf[ks][2], qf[ks][3], b0, b1);
                mma16816(c_[2 * j2 + 1], qf[ks][0], qf[ks][1], qf[ks][2], qf[ks][3], b2, b3);
            }
        }

        if (kt == nt - 1) {
            const int row0 = q0 + w * 16 + grow;
            const int k0   = kt * 64;
            #pragma unroll
            for (int j = 0; j < 8; j++) {
                const int col = k0 + j * 8 + gcol;
                if (col     > row0)     c_[j][0] = -1e30f;
                if (col + 1 > row0)     c_[j][1] = -1e30f;
                if (col     > row0 + 8) c_[j][2] = -1e30f;
                if (col + 1 > row0 + 8) c_[j][3] = -1e30f;
            }
        }

        float tm0 = -1e30f, tm1 = -1e30f;
        #pragma unroll
        for (int j = 0; j < 8; j++) {
            tm0 = fmaxf(tm0, fmaxf(c_[j][0], c_[j][1]));
            tm1 = fmaxf(tm1, fmaxf(c_[j][2], c_[j][3]));
        }
        tm0 = fmaxf(tm0, __shfl_xor_sync(0xffffffffu, tm0, 1));
        tm0 = fmaxf(tm0, __shfl_xor_sync(0xffffffffu, tm0, 2));
        tm1 = fmaxf(tm1, __shfl_xor_sync(0xffffffffu, tm1, 1));
        tm1 = fmaxf(tm1, __shfl_xor_sync(0xffffffffu, tm1, 2));
        const float mn0 = fmaxf(m0, tm0), mn1 = fmaxf(m1, tm1);
        const float corr0 = exp2_poly((m0 - mn0) * L2E);
        const float corr1 = exp2_poly((m1 - mn1) * L2E);
        m0 = mn0; m1 = mn1;

        uint32_t ph[8][2];
        float s0 = 0.0f, s1 = 0.0f;
        #pragma unroll
        for (int j = 0; j < 8; j++) {
            ph[j][0] = exp2_h2((c_[j][0] - mn0) * L2E, (c_[j][1] - mn0) * L2E);
            float2 p0 = __half22float2(*(__half2*)&ph[j][0]);
            s0 += p0.x + p0.y;
            const float e2 = exp2_poly((c_[j][2] - mn1) * L2E);
            const float e3 = exp2_poly((c_[j][3] - mn1) * L2E);
            __half2 hh2 = __floats2half2_rn(e2, e3);
            ph[j][1] = *(uint32_t*)&hh2;
            s1 += e2 + e3;
        }
        s0 += __shfl_xor_sync(0xffffffffu, s0, 1);
        s0 += __shfl_xor_sync(0xffffffffu, s0, 2);
        s1 += __shfl_xor_sync(0xffffffffu, s1, 1);
        s1 += __shfl_xor_sync(0xffffffffu, s1, 2);
        l0 = l0 * corr0 + s0;
        l1 = l1 * corr1 + s1;
        #pragma unroll
        for (int j = 0; j < 8; j++) {
            o[j][0] *= corr0; o[j][1] *= corr0;
            o[j][2] *= corr1; o[j][3] *= corr1;
        }

        #pragma unroll
        for (int ks = 0; ks < 4; ks++) {
            const uint32_t a0 = ph[2 * ks][0],     a1 = ph[2 * ks][1];
            const uint32_t a2 = ph[2 * ks + 1][0], a3 = ph[2 * ks + 1][1];
            #pragma unroll
            for (int j2 = 0; j2 < 4; j2++) {
                uint32_t b0, b1, b2, b3;
                ldsm4t(b0, b1, b2, b3, bV_ + voff + (uint32_t)(ks * 16 * ALD + j2 * 16) * 2);
                mma16816(o[2 * j2],     a0, a1, a2, a3, b0, b1);
                mma16816(o[2 * j2 + 1], a0, a1, a2, a3, b2, b3);
            }
        }
        __syncthreads();
    }

    const int b = bh / NH, h = bh % NH;
    const float i0 = __fdividef(1.0f, l0), i1 = __fdividef(1.0f, l1);
    const int row0 = q0 + w * 16 + grow;
    const size_t t0 = (size_t)b * SEQ + row0;
    const size_t t1 = t0 + 8;
    #pragma unroll
    for (int j = 0; j < 8; j++) {
        const int col = h * DH + j * 8 + gcol;
        *(__half2*)&Z[t0 * DM + col] = __floats2half2_rn(o[j][0] * i0, o[j][1] * i0);
        *(__half2*)&Z[t1 * DM + col] = __floats2half2_rn(o[j][2] * i1, o[j][3] * i1);
    }
}

// ---------------- launch --------------------------------------------------------
extern "C" void kernel_launch(void* const* d_in, const int* in_sizes, int n_in,
                              void* d_out, int out_size) {
    const float* resid_pre = (const float*)d_in[0];
    const float* W_Q  = (const float*)d_in[1];
    const float* b_Q  = (const float*)d_in[2];
    const float* W_K  = (const float*)d_in[3];
    const float* b_K  = (const float*)d_in[4];
    const float* W_V  = (const float*)d_in[5];
    const float* b_V  = (const float*)d_in[6];
    const float* W_O  = (const float*)d_in[7];
    const float* b_O  = (const float*)d_in[8];
    const float* ln1w = (const float*)d_in[9];
    const float* ln1b = (const float*)d_in[10];
    const float* ln2w = (const float*)d_in[11];
    const float* ln2b = (const float*)d_in[12];
    const float* W_in = (const float*)d_in[13];
    const float* b_in = (const float*)d_in[14];
    const float* W_out= (const float*)d_in[15];
    const float* b_out= (const float*)d_in[16];
    float* out = (float*)d_out;

    __half *n1h, *zh, *n2h, *hh, *WqkvT, *WoT, *WinT, *WoutT, *q, *k, *v;
    float *rm, *qkvb;
    cudaGetSymbolAddress((void**)&n1h,  g_n1h);
    cudaGetSymbolAddress((void**)&q,    g_q);
    cudaGetSymbolAddress((void**)&k,    g_k);
    cudaGetSymbolAddress((void**)&v,    g_v);
    cudaGetSymbolAddress((void**)&zh,   g_zh);
    cudaGetSymbolAddress((void**)&rm,   g_rm);
    cudaGetSymbolAddress((void**)&n2h,  g_n2h);
    cudaGetSymbolAddress((void**)&hh,   g_hh);
    cudaGetSymbolAddress((void**)&WqkvT,g_WqkvT);
    cudaGetSymbolAddress((void**)&WoT,  g_WoT);
    cudaGetSymbolAddress((void**)&WinT, g_WinT);
    cudaGetSymbolAddress((void**)&WoutT,g_WoutT);
    cudaGetSymbolAddress((void**)&qkvb, g_qkvb);

    cudaFuncSetAttribute((const void*)mma_gemm<0>, cudaFuncAttributeMaxDynamicSharedMemorySize, GEMM_SMEM);
    cudaFuncSetAttribute((const void*)mma_gemm<1>, cudaFuncAttributeMaxDynamicSharedMemorySize, GEMM_SMEM);
    cudaFuncSetAttribute((const void*)mma_gemm<2>, cudaFuncAttributeMaxDynamicSharedMemorySize, GEMM_SMEM);
    cudaFuncSetAttribute((const void*)attn_mma,    cudaFuncAttributeMaxDynamicSharedMemorySize, ATTN_SMEM);

    prep_all<<<6921, dim3(32, 8)>>>(W_Q, W_K, W_V, W_O, W_in, W_out,
                                    b_Q, b_K, b_V,
                                    WqkvT, WoT, WinT, WoutT, qkvb);

    ln_kernel<<<TOK, 256>>>(resid_pre, ln1w, ln1b, n1h);
    mma_gemm<2><<<dim3(18, 64), 128, GEMM_SMEM>>>(n1h, WqkvT, qkvb, nullptr,
                                                  nullptr, nullptr, q, k, v, 3*DM, DM);
    attn_mma<<<dim3(16, 96), 128, ATTN_SMEM>>>(q, k, v, zh);
    mma_gemm<0><<<dim3(6, 64), 128, GEMM_SMEM>>>(zh, WoT, b_O, resid_pre,
                                                 rm, nullptr, nullptr, nullptr, nullptr, DM, DM);
    ln_kernel<<<TOK, 256>>>(rm, ln2w, ln2b, n2h);
    mma_gemm<1><<<dim3(24, 64), 128, GEMM_SMEM>>>(n2h, WinT, b_in, nullptr,
                                                  nullptr, hh, nullptr, nullptr, nullptr, DMLP, DM);
    mma_gemm<0><<<dim3(6, 64), 128, GEMM_SMEM>>>(hh, WoutT, b_out, rm,
                                                 out, nullptr, nullptr, nullptr, nullptr, DM, DMLP);
}

// round 14
// speedup vs baseline: 1.0291x; 1.0291x over previous
#include <cuda_runtime.h>
#include <cuda_fp16.h>
#include <cstdint>

#define TOK 8192
#define SEQ 1024
#define DM  768
#define NH  12
#define DH  64
#define DMLP 3072

// ---------------- scratch ----------------------------------------------------
__device__ __half g_n1h[TOK*DM];
__device__ __half g_q [TOK*DM];
__device__ __half g_k [TOK*DM];
__device__ __half g_v [TOK*DM];
__device__ __half g_zh[TOK*DM];
__device__ float  g_rm[TOK*DM];
__device__ float  g_p0[TOK*DM];
__device__ float  g_p1[TOK*DM];
__device__ __half g_n2h[TOK*DM];
__device__ __half g_hh[TOK*DMLP];
__device__ __half g_WqkvT[3*DM*DM];
__device__ __half g_WoT  [DM*DM];
__device__ __half g_WinT [DMLP*DM];
__device__ __half g_WoutT[DM*DMLP];
__device__ float  g_qkvb[3*DM];

typedef unsigned long long u64;

__device__ __forceinline__ float gelu_new(float x) {
    float x3 = x * x * x;
    float t  = tanhf(0.7978845608028654f * (x + 0.044715f * x3));
    return 0.5f * x * (1.0f + t);
}

// ---------------- mma / ldmatrix / cp.async helpers ----------------------------
__device__ __forceinline__ uint32_t smem_u32(const void* p) {
    uint32_t a;
    asm("{ .reg .u64 t; cvta.to.shared.u64 t, %1; cvt.u32.u64 %0, t; }" : "=r"(a) : "l"(p));
    return a;
}
__device__ __forceinline__ void cpasync16(uint32_t dst, const void* src) {
    asm volatile("cp.async.cg.shared.global [%0], [%1], 16;" :: "r"(dst), "l"(src));
}
#define CP_COMMIT() asm volatile("cp.async.commit_group;" ::: "memory")
#define CP_WAIT1()  asm volatile("cp.async.wait_group 1;" ::: "memory")
#define CP_WAIT0()  asm volatile("cp.async.wait_group 0;" ::: "memory")

__device__ __forceinline__ void ldsm4(uint32_t &r0, uint32_t &r1, uint32_t &r2, uint32_t &r3,
                                      uint32_t addr) {
    asm volatile("ldmatrix.sync.aligned.m8n8.x4.shared.b16 {%0,%1,%2,%3}, [%4];"
                 : "=r"(r0), "=r"(r1), "=r"(r2), "=r"(r3) : "r"(addr));
}
__device__ __forceinline__ void ldsm4t(uint32_t &r0, uint32_t &r1, uint32_t &r2, uint32_t &r3,
                                       uint32_t addr) {
    asm volatile("ldmatrix.sync.aligned.m8n8.x4.trans.shared.b16 {%0,%1,%2,%3}, [%4];"
                 : "=r"(r0), "=r"(r1), "=r"(r2), "=r"(r3) : "r"(addr));
}
__device__ __forceinline__ void mma16816(float* c, uint32_t a0, uint32_t a1, uint32_t a2,
                                         uint32_t a3, uint32_t b0, uint32_t b1) {
    asm volatile("mma.sync.aligned.m16n8k16.row.col.f32.f16.f16.f32 "
                 "{%0,%1,%2,%3},{%4,%5,%6,%7},{%8,%9},{%0,%1,%2,%3};"
                 : "+f"(c[0]), "+f"(c[1]), "+f"(c[2]), "+f"(c[3])
                 : "r"(a0), "r"(a1), "r"(a2), "r"(a3), "r"(b0), "r"(b1));
}
__device__ __forceinline__ uint32_t exp2_h2(float e0, float e1) {
    __half2 h = __floats2half2_rn(e0, e1);
    uint32_t hi = *(uint32_t*)&h, r;
    asm("ex2.approx.f16x2 %0, %1;" : "=r"(r) : "r"(hi));
    return r;
}
__device__ __forceinline__ float exp2_poly(float t) {
    t = fmaxf(t, -30.0f);
    const float z = t + 12582912.0f;
    const int   n = __float_as_int(z) << 23;
    const float f = t - (z - 12582912.0f);
    float p = 0.009618129f;
    p = fmaf(p, f, 0.05550411f);
    p = fmaf(p, f, 0.24022651f);
    p = fmaf(p, f, 0.69314718f);
    p = fmaf(p, f, 1.0f);
    return __int_as_float(__float_as_int(p) + n);
}

// ---------------- HMMA GEMM: BK=64, 3 stages, 8 warps, warp tile 64x32 ----------
// EPI 0: C = acc+bias+R | EPI 1: Ch = gelu(acc+bias) | EPI 2: q/k/v scatter
// EPI 3: raw fp32 partial into C (z=0) / C2 (z=1), split-K via blockIdx.z
#define LDSH 72
#define STG_H (2 * 128 * LDSH)
#define GEMM_SMEM (3 * STG_H * 2)        // 110592 B

template<int EPI>
__global__ void __launch_bounds__(256, 2) mma_gemm(
    const __half* __restrict__ A, const __half* __restrict__ Bt,
    const float* __restrict__ bias, const float* __restrict__ R,
    float* __restrict__ C, float* __restrict__ C2, __half* __restrict__ Ch,
    __half* __restrict__ Qp, __half* __restrict__ Kp, __half* __restrict__ Vp,
    int N, int K, int klen)
{
    extern __shared__ __half sm[];
    const int tid  = threadIdx.x;
    const int lane = tid & 31, wid = tid >> 5;
    const int wm = wid >> 2, wn = wid & 3;
    const int col0 = blockIdx.x * 128;
    const int row0 = blockIdx.y * 128;
    const int kbase = blockIdx.z * klen;
    const int KT = klen / 64;

    const uint32_t sbase = smem_u32(sm);

    float acc[4][4][4];
    #pragma unroll
    for (int i = 0; i < 4; i++)
        #pragma unroll
        for (int j = 0; j < 4; j++)
            #pragma unroll
            for (int x = 0; x < 4; x++) acc[i][j][x] = 0.0f;

    auto load_stage = [&](int s, int kt) {
        const uint32_t st = sbase + (uint32_t)s * (STG_H * 2);
        const int kk = kbase + kt * 64;
        #pragma unroll
        for (int h = 0; h < 4; h++) {
            const int c  = tid + h * 256;
            const int r  = c >> 3;
            const int kc = (c & 7) * 8;
            cpasync16(st + (uint32_t)(r * LDSH + kc) * 2,
                      A + (size_t)(row0 + r) * K + kk + kc);
            cpasync16(st + (uint32_t)((128 + r) * LDSH + kc) * 2,
                      Bt + (size_t)(col0 + r) * K + kk + kc);
        }
    };

    auto compute_stage = [&](int s) {
        const uint32_t aB = sbase + (uint32_t)s * (STG_H * 2);
        const uint32_t bB = aB + 128 * LDSH * 2;
        const int lrow = lane & 15;
        const int lcol = (lane >> 4) * 8;
        #pragma unroll
        for (int ks = 0; ks < 4; ks++) {
            const int ko = ks * 16 + lcol;
            uint32_t af[4][4];
            #pragma unroll
            for (int i = 0; i < 4; i++) {
                const int row = wm * 64 + i * 16 + lrow;
                ldsm4(af[i][0], af[i][1], af[i][2], af[i][3],
                      aB + (uint32_t)(row * LDSH + ko) * 2);
            }
            uint32_t bf[2][4];
            #pragma unroll
            for (int j = 0; j < 2; j++) {
                const int row = wn * 32 + j * 16 + lrow;
                ldsm4(bf[j][0], bf[j][1], bf[j][2], bf[j][3],
                      bB + (uint32_t)(row * LDSH + ko) * 2);
            }
            #pragma unroll
            for (int i = 0; i < 4; i++)
                #pragma unroll
                for (int j = 0; j < 4; j++)
                    mma16816(acc[i][j], af[i][0], af[i][1], af[i][2], af[i][3],
                             bf[j >> 1][j & 1], bf[j >> 1][(j & 1) + 2]);
        }
    };

    load_stage(0, 0); CP_COMMIT();
    load_stage(1, 1); CP_COMMIT();

    int sidx = 0;
    for (int kt = 0; kt < KT; kt++) {
        CP_WAIT1();
        __syncthreads();
        if (kt + 2 < KT) {
            int ns = sidx + 2; if (ns >= 3) ns -= 3;
            load_stage(ns, kt + 2);
        }
        CP_COMMIT();
        compute_stage(sidx);
        if (++sidx == 3) sidx = 0;
    }

    float* Cz = (EPI == 3 && blockIdx.z) ? C2 : C;

    const int g = lane >> 2, t4 = lane & 3;
    #pragma unroll
    for (int i = 0; i < 4; i++) {
        const int r0g = row0 + wm * 64 + i * 16 + g;
        #pragma unroll
        for (int j = 0; j < 4; j++) {
            const int c0g = col0 + wn * 32 + j * 8 + t4 * 2;
            float* a = acc[i][j];
            if (EPI == 3) {
                *(float2*)&Cz[(size_t)r0g * N + c0g]       = make_float2(a[0], a[1]);
                *(float2*)&Cz[(size_t)(r0g + 8) * N + c0g] = make_float2(a[2], a[3]);
                continue;
            }
            const float b0 = __ldg(&bias[c0g]);
            const float b1 = __ldg(&bias[c0g + 1]);
            if (EPI == 0) {
                float2 rA = *(const float2*)&R[(size_t)r0g * N + c0g];
                float2 rB = *(const float2*)&R[(size_t)(r0g + 8) * N + c0g];
                *(float2*)&C[(size_t)r0g * N + c0g] =
                    make_float2(a[0] + b0 + rA.x, a[1] + b1 + rA.y);
                *(float2*)&C[(size_t)(r0g + 8) * N + c0g] =
                    make_float2(a[2] + b0 + rB.x, a[3] + b1 + rB.y);
            } else if (EPI == 1) {
                *(__half2*)&Ch[(size_t)r0g * N + c0g] =
                    __floats2half2_rn(gelu_new(a[0] + b0), gelu_new(a[1] + b1));
                *(__half2*)&Ch[(size_t)(r0g + 8) * N + c0g] =
                    __floats2half2_rn(gelu_new(a[2] + b0), gelu_new(a[3] + b1));
            } else {
                const int which = c0g / DM;
                const int h2    = (c0g % DM) >> 6;
                const int e0    = c0g & 63;
                const float sc  = (which == 0) ? 0.125f : 1.0f;
                __half* OP = (which == 0) ? Qp : ((which == 1) ? Kp : Vp);
                __half* p0 = OP + ((size_t)((r0g >> 10) * NH + h2)) * (SEQ * DH)
                               + (size_t)(r0g & (SEQ - 1)) * DH + e0;
                __half* p1 = OP + ((size_t)(((r0g + 8) >> 10) * NH + h2)) * (SEQ * DH)
                               + (size_t)((r0g + 8) & (SEQ - 1)) * DH + e0;
                *(__half2*)p0 = __floats2half2_rn((a[0] + b0) * sc, (a[1] + b1) * sc);
                *(__half2*)p1 = __floats2half2_rn((a[2] + b0) * sc, (a[3] + b1) * sc);
            }
        }
    }
}

// ---------------- merged prep + LN1 (one launch, round-11 proven) ---------------
__device__ __forceinline__ void tr_tile(const float* __restrict__ in,
                                        __half* __restrict__ out,
                                        int C, int ldo, int c0, int r0,
                                        float* t, int tx, int ty)
{
    #pragma unroll
    for (int i = 0; i < 32; i += 8)
        t[(ty + i) * 33 + tx] = in[(size_t)(r0 + ty + i) * C + c0 + tx];
    __syncthreads();
    #pragma unroll
    for (int i = 0; i < 32; i += 8)
        out[(size_t)(c0 + ty + i) * ldo + r0 + tx] = __float2half(t[tx * 33 + ty + i]);
}

__device__ __forceinline__ void ln_row(const float* __restrict__ w,
                                       const float* __restrict__ b,
                                       __half* __restrict__ y, int t,
                                       float v0, float v1, float v2, float* sh)
{
    float s = v0 + v1 + v2;
    float q = v0 * v0 + v1 * v1 + v2 * v2;
    #pragma unroll
    for (int o = 16; o > 0; o >>= 1) {
        s += __shfl_xor_sync(0xffffffffu, s, o);
        q += __shfl_xor_sync(0xffffffffu, q, o);
    }
    const int lane = t & 31, wid = t >> 5;
    if (lane == 0) { sh[wid] = s; sh[wid + 8] = q; }
    __syncthreads();
    if (t == 0) {
        float ss = 0.f, qq = 0.f;
        #pragma unroll
        for (int i = 0; i < 8; i++) { ss += sh[i]; qq += sh[i + 8]; }
        sh[0] = ss; sh[8] = qq;
    }
    __syncthreads();
    s = sh[0]; q = sh[8];
    const float mu  = s * (1.0f / DM);
    const float inv = rsqrtf(q * (1.0f / DM) - mu * mu + 1e-5f);
    y[t]       = __float2half((v0 - mu) * inv * w[t]       + b[t]);
    y[t + 256] = __float2half((v1 - mu) * inv * w[t + 256] + b[t + 256]);
    y[t + 512] = __float2half((v2 - mu) * inv * w[t + 512] + b[t + 512]);
}

__global__ void __launch_bounds__(256) prep_ln1(
    const float* __restrict__ WQ, const float* __restrict__ WK, const float* __restrict__ WV,
    const float* __restrict__ WO, const float* __restrict__ Win, const float* __restrict__ Wout,
    const float* __restrict__ bq, const float* __restrict__ bk, const float* __restrict__ bv,
    __half* __restrict__ WqkvT, __half* __restrict__ WoT,
    __half* __restrict__ WinT,  __half* __restrict__ WoutT,
    float* __restrict__ qkvb,
    const float* __restrict__ X, const float* __restrict__ ln1w,
    const float* __restrict__ ln1b, __half* __restrict__ n1h)
{
    __shared__ float t[32 * 33];
    const int bid = blockIdx.x;
    const int tid = threadIdx.x;
    const int tx = tid & 31, ty = tid >> 5;

    if (bid < 1728) {
        const int which = bid / 576;
        const int r = bid % 576;
        const int h = r / 48, u = r % 48;
        const int c0 = (u & 1) * 32, r0 = (u >> 1) * 32;
        const float* in = ((which == 0) ? WQ : (which == 1) ? WK : WV) + (size_t)h * DM * DH;
        __half* out = WqkvT + (size_t)which * DM * DM + (size_t)h * DH * DM;
        tr_tile(in, out, DH, DM, c0, r0, t, tx, ty);
    } else if (bid < 2304) {
        const int r = bid - 1728;
        const int h = r / 48, u = r % 48;
        const int c0 = (u % 24) * 32, r0 = (u / 24) * 32;
        tr_tile(WO + (size_t)h * DH * DM, WoT + h * DH, DM, DM, c0, r0, t, tx, ty);
    } else if (bid < 4608) {
        const int r = bid - 2304;
        const int c0 = (r % 96) * 32, r0 = (r / 96) * 32;
        tr_tile(Win, WinT, DMLP, DM, c0, r0, t, tx, ty);
    } else if (bid < 6912) {
        const int r = bid - 4608;
        const int c0 = (r % 24) * 32, r0 = (r / 24) * 32;
        tr_tile(Wout, WoutT, DM, DMLP, c0, r0, t, tx, ty);
    } else if (bid < 6921) {
        const int n = (bid - 6912) * 256 + tid;
        if (n < 3 * DM) {
            const float* s = (n < DM) ? bq : ((n < 2 * DM) ? bk : bv);
            qkvb[n] = s[n % DM];
        }
    } else {
        const int row = bid - 6921;
        const float* x = X + (size_t)row * DM;
        ln_row(ln1w, ln1b, n1h + (size_t)row * DM, tid,
               x[tid], x[tid + 256], x[tid + 512], t);
    }
}

// ---------------- LayerNorm (fp32 in -> fp16 out), used for LN2 ------------------
__global__ void __launch_bounds__(256) ln_kernel(
    const float* __restrict__ X, const float* __restrict__ w,
    const float* __restrict__ b, __half* __restrict__ Y)
{
    __shared__ float sh[16];
    const int row = blockIdx.x;
    const float* x = X + (size_t)row * DM;
    const int t = threadIdx.x;
    ln_row(w, b, Y + (size_t)row * DM, t, x[t], x[t + 256], x[t + 512], sh);
}

// ---------------- final add (MLP-out split-K reduce + residual + bias) -----------
__global__ void __launch_bounds__(256) final_add(
    const float* __restrict__ rm, const float* __restrict__ P0,
    const float* __restrict__ P1, const float* __restrict__ bout,
    float* __restrict__ out)
{
    const size_t i4 = ((size_t)blockIdx.x * 256 + threadIdx.x) * 4;
    const int col = (int)(i4 % DM);
    float4 r  = *(const float4*)&rm[i4];
    float4 a  = *(const float4*)&P0[i4];
    float4 b_ = *(const float4*)&P1[i4];
    float4 bb = *(const float4*)&bout[col];
    float4 o;
    o.x = r.x + a.x + b_.x + bb.x;
    o.y = r.y + a.y + b_.y + bb.y;
    o.z = r.z + a.z + b_.z + bb.z;
    o.w = r.w + a.w + b_.w + bb.w;
    *(float4*)&out[i4] = o;
}

// ---------------- tensor-core causal flash attention (round-5 best) -------------
#define ALD 72
#define ATTN_SMEM ((64 + 128 + 128) * ALD * 2)
#define L2E 1.4426950408889634f

__global__ void __launch_bounds__(128) attn_mma(
    const __half* __restrict__ Q, const __half* __restrict__ K,
    const __half* __restrict__ V, __half* __restrict__ Z)
{
    extern __shared__ __half as_[];
    __half* Qs = as_;
    __half* Ks = as_ + 64 * ALD;
    __half* Vs = as_ + (64 + 128) * ALD;

    const int tid  = threadIdx.x;
    const int lane = tid & 31;
    const int w    = tid >> 5;
    const int bh   = blockIdx.y;
    const int q0   = (15 - blockIdx.x) * 64;
    const int nt   = q0 / 64 + 1;

    const __half* Qb = Q + (size_t)bh * (SEQ * DH);
    const __half* Kb = K + (size_t)bh * (SEQ * DH);
    const __half* Vb = V + (size_t)bh * (SEQ * DH);

    const uint32_t sQ = smem_u32(Qs);
    const uint32_t sK = smem_u32(Ks);
    const uint32_t sV = smem_u32(Vs);

    #pragma unroll
    for (int i = 0; i < 4; i++) {
        int c = tid + i * 128;
        int row = c >> 3, col = (c & 7) * 8;
        *(float4*)&Qs[row * ALD + col] = *(const float4*)&Qb[(size_t)(q0 + row) * DH + col];
    }

    auto load_kv = [&](int kt, int buf) {
        const int k0 = kt * 64;
        const uint32_t bK_ = sK + (uint32_t)buf * (64 * ALD * 2);
        const uint32_t bV_ = sV + (uint32_t)buf * (64 * ALD * 2);
        #pragma unroll
        for (int i = 0; i < 4; i++) {
            int c = tid + i * 128;
            int row = c >> 3, col = (c & 7) * 8;
            cpasync16(bK_ + (uint32_t)(row * ALD + col) * 2,
                      Kb + (size_t)(k0 + row) * DH + col);
            cpasync16(bV_ + (uint32_t)(row * ALD + col) * 2,
                      Vb + (size_t)(k0 + row) * DH + col);
        }
    };

    load_kv(0, 0); CP_COMMIT();
    __syncthreads();

    uint32_t qf[4][4];
    {
        const uint32_t qoff = sQ + (uint32_t)((w * 16 + (lane & 15)) * ALD + (lane >> 4) * 8) * 2;
        #pragma unroll
        for (int ks = 0; ks < 4; ks++)
            ldsm4(qf[ks][0], qf[ks][1], qf[ks][2], qf[ks][3], qoff + ks * 32);
    }

    float o[8][4];
    #pragma unroll
    for (int j = 0; j < 8; j++)
        #pragma unroll
        for (int x = 0; x < 4; x++) o[j][x] = 0.0f;
    float m0 = -1e30f, m1 = -1e30f, l0 = 0.0f, l1 = 0.0f;

    const uint32_t koff = (uint32_t)(((lane >> 4) * 8 + (lane & 7)) * ALD + ((lane >> 3) & 1) * 8) * 2;
    const uint32_t voff = (uint32_t)(((lane & 7) + ((lane >> 3) & 1) * 8) * ALD + (lane >> 4) * 8) * 2;
    const int grow = lane >> 2, gcol = (lane & 3) * 2;

    for (int kt = 0; kt < nt; kt++) {
        const int buf = kt & 1;
        if (kt + 1 < nt) { load_kv(kt + 1, buf ^ 1); CP_COMMIT(); CP_WAIT1(); }
        else            { CP_WAIT0(); }
        __syncthreads();

        const uint32_t bK_ = sK + (uint32_t)buf * (64 * ALD * 2);
        const uint32_t bV_ = sV + (uint32_t)buf * (64 * ALD * 2);

        float c_[8][4];
        #pragma unroll
        for (int j = 0; j < 8; j++)
            #pragma unroll
            for (int x = 0; x < 4; x++) c_[j][x] = 0.0f;
        #pragma unroll
        for (int ks = 0; ks < 4; ks++) {
            #pragma unroll
            for (int j2 = 0; j2 < 4; j2++) {
                uint32_t b0, b1, b2, b3;
                ldsm4(b0, b1, b2, b3, bK_ + koff + (uint32_t)(j2 * 16 * ALD + ks * 16) * 2);
                mma16816(c_[2 * j2],     qf[ks][0], qf[ks][1], qf[ks][2], qf[ks][3], b0, b1);
                mma16816(c_[2 * j2 + 1], qf[ks][0], qf[ks][1], qf[ks][2], qf[ks][3], b2, b3);
            }
        }

        if (kt == nt - 1) {
            const int row0 = q0 + w * 16 + grow;
            const int k0   = kt * 64;
            #pragma unroll
            for (int j = 0; j < 8; j++) {
                const int col = k0 + j * 8 + gcol;
                if (col     > row0)     c_[j][0] = -1e30f;
                if (col + 1 > row0)     c_[j][1] = -1e30f;
                if (col     > row0 + 8) c_[j][2] = -1e30f;
                if (col + 1 > row0 + 8) c_[j][3] = -1e30f;
            }
        }

        float tm0 = -1e30f, tm1 = -1e30f;
        #pragma unroll
        for (int j = 0; j < 8; j++) {
            tm0 = fmaxf(tm0, fmaxf(c_[j][0], c_[j][1]));
            tm1 = fmaxf(tm1, fmaxf(c_[j][2], c_[j][3]));
        }
        tm0 = fmaxf(tm0, __shfl_xor_sync(0xffffffffu, tm0, 1));
        tm0 = fmaxf(tm0, __shfl_xor_sync(0xffffffffu, tm0, 2));
        tm1 = fmaxf(tm1, __shfl_xor_sync(0xffffffffu, tm1, 1));
        tm1 = fmaxf(tm1, __shfl_xor_sync(0xffffffffu, tm1, 2));
        const float mn0 = fmaxf(m0, tm0), mn1 = fmaxf(m1, tm1);
        const float corr0 = exp2_poly((m0 - mn0) * L2E);
        const float corr1 = exp2_poly((m1 - mn1) * L2E);
        m0 = mn0; m1 = mn1;

        uint32_t ph[8][2];
        float s0 = 0.0f, s1 = 0.0f;
        #pragma unroll
        for (int j = 0; j < 8; j++) {
            ph[j][0] = exp2_h2((c_[j][0] - mn0) * L2E, (c_[j][1] - mn0) * L2E);
            float2 p0 = __half22float2(*(__half2*)&ph[j][0]);
            s0 += p0.x + p0.y;
            const float e2 = exp2_poly((c_[j][2] - mn1) * L2E);
            const float e3 = exp2_poly((c_[j][3] - mn1) * L2E);
            __half2 hh2 = __floats2half2_rn(e2, e3);
            ph[j][1] = *(uint32_t*)&hh2;
            s1 += e2 + e3;
        }
        s0 += __shfl_xor_sync(0xffffffffu, s0, 1);
        s0 += __shfl_xor_sync(0xffffffffu, s0, 2);
        s1 += __shfl_xor_sync(0xffffffffu, s1, 1);
        s1 += __shfl_xor_sync(0xffffffffu, s1, 2);
        l0 = l0 * corr0 + s0;
        l1 = l1 * corr1 + s1;
        #pragma unroll
        for (int j = 0; j < 8; j++) {
            o[j][0] *= corr0; o[j][1] *= corr0;
            o[j][2] *= corr1; o[j][3] *= corr1;
        }

        #pragma unroll
        for (int ks = 0; ks < 4; ks++) {
            const uint32_t a0 = ph[2 * ks][0],     a1 = ph[2 * ks][1];
            const uint32_t a2 = ph[2 * ks + 1][0], a3 = ph[2 * ks + 1][1];
            #pragma unroll
            for (int j2 = 0; j2 < 4; j2++) {
                uint32_t b0, b1, b2, b3;
                ldsm4t(b0, b1, b2, b3, bV_ + voff + (uint32_t)(ks * 16 * ALD + j2 * 16) * 2);
                mma16816(o[2 * j2],     a0, a1, a2, a3, b0, b1);
                mma16816(o[2 * j2 + 1], a0, a1, a2, a3, b2, b3);
            }
        }
        __syncthreads();
    }

    const int b = bh / NH, h = bh % NH;
    const float i0 = __fdividef(1.0f, l0), i1 = __fdividef(1.0f, l1);
    const int row0 = q0 + w * 16 + grow;
    const size_t t0 = (size_t)b * SEQ + row0;
    const size_t t1 = t0 + 8;
    #pragma unroll
    for (int j = 0; j < 8; j++) {
        const int col = h * DH + j * 8 + gcol;
        *(__half2*)&Z[t0 * DM + col] = __floats2half2_rn(o[j][0] * i0, o[j][1] * i0);
        *(__half2*)&Z[t1 * DM + col] = __floats2half2_rn(o[j][2] * i1, o[j][3] * i1);
    }
}

// ---------------- launch --------------------------------------------------------
extern "C" void kernel_launch(void* const* d_in, const int* in_sizes, int n_in,
                              void* d_out, int out_size) {
    const float* resid_pre = (const float*)d_in[0];
    const float* W_Q  = (const float*)d_in[1];
    const float* b_Q  = (const float*)d_in[2];
    const float* W_K  = (const float*)d_in[3];
    const float* b_K  = (const float*)d_in[4];
    const float* W_V  = (const float*)d_in[5];
    const float* b_V  = (const float*)d_in[6];
    const float* W_O  = (const float*)d_in[7];
    const float* b_O  = (const float*)d_in[8];
    const float* ln1w = (const float*)d_in[9];
    const float* ln1b = (const float*)d_in[10];
    const float* ln2w = (const float*)d_in[11];
    const float* ln2b = (const float*)d_in[12];
    const float* W_in = (const float*)d_in[13];
    const float* b_in = (const float*)d_in[14];
    const float* W_out= (const float*)d_in[15];
    const float* b_out= (const float*)d_in[16];
    float* out = (float*)d_out;

    __half *n1h, *zh, *n2h, *hh, *WqkvT, *WoT, *WinT, *WoutT, *q, *k, *v;
    float *rm, *p0, *p1, *qkvb;
    cudaGetSymbolAddress((void**)&n1h,  g_n1h);
    cudaGetSymbolAddress((void**)&q,    g_q);
    cudaGetSymbolAddress((void**)&k,    g_k);
    cudaGetSymbolAddress((void**)&v,    g_v);
    cudaGetSymbolAddress((void**)&zh,   g_zh);
    cudaGetSymbolAddress((void**)&rm,   g_rm);
    cudaGetSymbolAddress((void**)&p0,   g_p0);
    cudaGetSymbolAddress((void**)&p1,   g_p1);
    cudaGetSymbolAddress((void**)&n2h,  g_n2h);
    cudaGetSymbolAddress((void**)&hh,   g_hh);
    cudaGetSymbolAddress((void**)&WqkvT,g_WqkvT);
    cudaGetSymbolAddress((void**)&WoT,  g_WoT);
    cudaGetSymbolAddress((void**)&WinT, g_WinT);
    cudaGetSymbolAddress((void**)&WoutT,g_WoutT);
    cudaGetSymbolAddress((void**)&qkvb, g_qkvb);

    cudaFuncSetAttribute((const void*)mma_gemm<0>, cudaFuncAttributeMaxDynamicSharedMemorySize, GEMM_SMEM);
    cudaFuncSetAttribute((const void*)mma_gemm<1>, cudaFuncAttributeMaxDynamicSharedMemorySize, GEMM_SMEM);
    cudaFuncSetAttribute((const void*)mma_gemm<2>, cudaFuncAttributeMaxDynamicSharedMemorySize, GEMM_SMEM);
    cudaFuncSetAttribute((const void*)mma_gemm<3>, cudaFuncAttributeMaxDynamicSharedMemorySize, GEMM_SMEM);
    cudaFuncSetAttribute((const void*)attn_mma,    cudaFuncAttributeMaxDynamicSharedMemorySize, ATTN_SMEM);

    // merged prep + LN1
    prep_ln1<<<6921 + TOK, 256>>>(W_Q, W_K, W_V, W_O, W_in, W_out,
                                  b_Q, b_K, b_V,
                                  WqkvT, WoT, WinT, WoutT, qkvb,
                                  resid_pre, ln1w, ln1b, n1h);

    // QKV projection
    mma_gemm<2><<<dim3(18, 64, 1), 256, GEMM_SMEM>>>(n1h, WqkvT, qkvb, nullptr,
                                                     nullptr, nullptr, nullptr,
                                                     q, k, v, 3*DM, DM, DM);
    attn_mma<<<dim3(16, 96), 128, ATTN_SMEM>>>(q, k, v, zh);

    // O-proj (unsplit, fused residual epilogue)
    mma_gemm<0><<<dim3(6, 64, 1), 256, GEMM_SMEM>>>(zh, WoT, b_O, resid_pre,
                                                    rm, nullptr, nullptr,
                                                    nullptr, nullptr, nullptr, DM, DM, DM);
    ln_kernel<<<TOK, 256>>>(rm, ln2w, ln2b, n2h);

    // MLP-in (gelu fused)
    mma_gemm<1><<<dim3(24, 64, 1), 256, GEMM_SMEM>>>(n2h, WinT, b_in, nullptr,
                                                     nullptr, nullptr, hh,
                                                     nullptr, nullptr, nullptr, DMLP, DM, DM);
    // MLP-out split-K=2 -> raw partials p0/p1
    mma_gemm<3><<<dim3(6, 64, 2), 256, GEMM_SMEM>>>(hh, WoutT, nullptr, nullptr,
                                                    p0, p1, nullptr,
                                                    nullptr, nullptr, nullptr, DM, DMLP, DMLP/2);
    // out = rm + p0 + p1 + b_out
    final_add<<<(TOK * DM) / 1024, 256>>>(rm, p0, p1, b_out, out);
}

// round 15
// speedup vs baseline: 1.0437x; 1.0142x over previous
#include <cuda_runtime.h>
#include <cuda_fp16.h>
#include <cstdint>

#define TOK 8192
#define SEQ 1024
#define DM  768
#define NH  12
#define DH  64
#define DMLP 3072

// ---------------- scratch ----------------------------------------------------
__device__ __half g_n1h[TOK*DM];
__device__ __half g_q [TOK*DM];
__device__ __half g_k [TOK*DM];
__device__ __half g_v [TOK*DM];
__device__ __half g_zh[TOK*DM];
__device__ float  g_rm[TOK*DM];
__device__ __half g_n2h[TOK*DM];
__device__ __half g_hh[TOK*DMLP];
__device__ __half g_WqkvT[3*DM*DM];
__device__ __half g_WoT  [DM*DM];
__device__ __half g_WinT [DMLP*DM];
__device__ __half g_WoutT[DM*DMLP];
__device__ float  g_qkvb[3*DM];

typedef unsigned long long u64;

__device__ __forceinline__ float gelu_new(float x) {
    float x3 = x * x * x;
    float t  = tanhf(0.7978845608028654f * (x + 0.044715f * x3));
    return 0.5f * x * (1.0f + t);
}

// ---------------- mma / ldmatrix / cp.async helpers ----------------------------
__device__ __forceinline__ uint32_t smem_u32(const void* p) {
    uint32_t a;
    asm("{ .reg .u64 t; cvta.to.shared.u64 t, %1; cvt.u32.u64 %0, t; }" : "=r"(a) : "l"(p));
    return a;
}
__device__ __forceinline__ void cpasync16(uint32_t dst, const void* src) {
    asm volatile("cp.async.cg.shared.global [%0], [%1], 16;" :: "r"(dst), "l"(src));
}
#define CP_COMMIT() asm volatile("cp.async.commit_group;" ::: "memory")
#define CP_WAIT1()  asm volatile("cp.async.wait_group 1;" ::: "memory")
#define CP_WAIT0()  asm volatile("cp.async.wait_group 0;" ::: "memory")

__device__ __forceinline__ void ldsm4(uint32_t &r0, uint32_t &r1, uint32_t &r2, uint32_t &r3,
                                      uint32_t addr) {
    asm volatile("ldmatrix.sync.aligned.m8n8.x4.shared.b16 {%0,%1,%2,%3}, [%4];"
                 : "=r"(r0), "=r"(r1), "=r"(r2), "=r"(r3) : "r"(addr));
}
__device__ __forceinline__ void ldsm4t(uint32_t &r0, uint32_t &r1, uint32_t &r2, uint32_t &r3,
                                       uint32_t addr) {
    asm volatile("ldmatrix.sync.aligned.m8n8.x4.trans.shared.b16 {%0,%1,%2,%3}, [%4];"
                 : "=r"(r0), "=r"(r1), "=r"(r2), "=r"(r3) : "r"(addr));
}
__device__ __forceinline__ void mma16816(float* c, uint32_t a0, uint32_t a1, uint32_t a2,
                                         uint32_t a3, uint32_t b0, uint32_t b1) {
    asm volatile("mma.sync.aligned.m16n8k16.row.col.f32.f16.f16.f32 "
                 "{%0,%1,%2,%3},{%4,%5,%6,%7},{%8,%9},{%0,%1,%2,%3};"
                 : "+f"(c[0]), "+f"(c[1]), "+f"(c[2]), "+f"(c[3])
                 : "r"(a0), "r"(a1), "r"(a2), "r"(a3), "r"(b0), "r"(b1));
}
__device__ __forceinline__ uint32_t exp2_h2(float e0, float e1) {
    __half2 h = __floats2half2_rn(e0, e1);
    uint32_t hi = *(uint32_t*)&h, r;
    asm("ex2.approx.f16x2 %0, %1;" : "=r"(r) : "r"(hi));
    return r;
}
__device__ __forceinline__ float exp2_poly(float t) {
    t = fmaxf(t, -30.0f);
    const float z = t + 12582912.0f;
    const int   n = __float_as_int(z) << 23;
    const float f = t - (z - 12582912.0f);
    float p = 0.009618129f;
    p = fmaf(p, f, 0.05550411f);
    p = fmaf(p, f, 0.24022651f);
    p = fmaf(p, f, 0.69314718f);
    p = fmaf(p, f, 1.0f);
    return __int_as_float(__float_as_int(p) + n);
}

// ---------------- HMMA GEMM: BK=64, 3 stages, 8 warps, warp tile 64x32 ----------
// (round-12 certified best config)
#define LDSH 72
#define STG_H (2 * 128 * LDSH)
#define GEMM_SMEM (3 * STG_H * 2)        // 110592 B

template<int EPI>
__global__ void __launch_bounds__(256, 2) mma_gemm(
    const __half* __restrict__ A, const __half* __restrict__ Bt,
    const float* __restrict__ bias, const float* __restrict__ R,
    float* __restrict__ C, __half* __restrict__ Ch,
    __half* __restrict__ Qp, __half* __restrict__ Kp, __half* __restrict__ Vp,
    int N, int K)
{
    extern __shared__ __half sm[];
    const int tid  = threadIdx.x;
    const int lane = tid & 31, wid = tid >> 5;
    const int wm = wid >> 2, wn = wid & 3;
    const int col0 = blockIdx.x * 128;
    const int row0 = blockIdx.y * 128;
    const int KT = K / 64;

    const uint32_t sbase = smem_u32(sm);

    float acc[4][4][4];
    #pragma unroll
    for (int i = 0; i < 4; i++)
        #pragma unroll
        for (int j = 0; j < 4; j++)
            #pragma unroll
            for (int x = 0; x < 4; x++) acc[i][j][x] = 0.0f;

    auto load_stage = [&](int s, int kt) {
        const uint32_t st = sbase + (uint32_t)s * (STG_H * 2);
        const int kk = kt * 64;
        #pragma unroll
        for (int h = 0; h < 4; h++) {
            const int c  = tid + h * 256;
            const int r  = c >> 3;
            const int kc = (c & 7) * 8;
            cpasync16(st + (uint32_t)(r * LDSH + kc) * 2,
                      A + (size_t)(row0 + r) * K + kk + kc);
            cpasync16(st + (uint32_t)((128 + r) * LDSH + kc) * 2,
                      Bt + (size_t)(col0 + r) * K + kk + kc);
        }
    };

    auto compute_stage = [&](int s) {
        const uint32_t aB = sbase + (uint32_t)s * (STG_H * 2);
        const uint32_t bB = aB + 128 * LDSH * 2;
        const int lrow = lane & 15;
        const int lcol = (lane >> 4) * 8;
        #pragma unroll
        for (int ks = 0; ks < 4; ks++) {
            const int ko = ks * 16 + lcol;
            uint32_t af[4][4];
            #pragma unroll
            for (int i = 0; i < 4; i++) {
                const int row = wm * 64 + i * 16 + lrow;
                ldsm4(af[i][0], af[i][1], af[i][2], af[i][3],
                      aB + (uint32_t)(row * LDSH + ko) * 2);
            }
            uint32_t bf[2][4];
            #pragma unroll
            for (int j = 0; j < 2; j++) {
                const int row = wn * 32 + j * 16 + lrow;
                ldsm4(bf[j][0], bf[j][1], bf[j][2], bf[j][3],
                      bB + (uint32_t)(row * LDSH + ko) * 2);
            }
            #pragma unroll
            for (int i = 0; i < 4; i++)
                #pragma unroll
                for (int j = 0; j < 4; j++)
                    mma16816(acc[i][j], af[i][0], af[i][1], af[i][2], af[i][3],
                             bf[j >> 1][j & 1], bf[j >> 1][(j & 1) + 2]);
        }
    };

    load_stage(0, 0); CP_COMMIT();
    load_stage(1, 1); CP_COMMIT();

    int sidx = 0;
    for (int kt = 0; kt < KT; kt++) {
        CP_WAIT1();
        __syncthreads();
        if (kt + 2 < KT) {
            int ns = sidx + 2; if (ns >= 3) ns -= 3;
            load_stage(ns, kt + 2);
        }
        CP_COMMIT();
        compute_stage(sidx);
        if (++sidx == 3) sidx = 0;
    }

    const int g = lane >> 2, t4 = lane & 3;
    #pragma unroll
    for (int i = 0; i < 4; i++) {
        const int r0g = row0 + wm * 64 + i * 16 + g;
        #pragma unroll
        for (int j = 0; j < 4; j++) {
            const int c0g = col0 + wn * 32 + j * 8 + t4 * 2;
            const float b0 = __ldg(&bias[c0g]);
            const float b1 = __ldg(&bias[c0g + 1]);
            float* a = acc[i][j];
            if (EPI == 0) {
                float2 rA = *(const float2*)&R[(size_t)r0g * N + c0g];
                float2 rB = *(const float2*)&R[(size_t)(r0g + 8) * N + c0g];
                *(float2*)&C[(size_t)r0g * N + c0g] =
                    make_float2(a[0] + b0 + rA.x, a[1] + b1 + rA.y);
                *(float2*)&C[(size_t)(r0g + 8) * N + c0g] =
                    make_float2(a[2] + b0 + rB.x, a[3] + b1 + rB.y);
            } else if (EPI == 1) {
                *(__half2*)&Ch[(size_t)r0g * N + c0g] =
                    __floats2half2_rn(gelu_new(a[0] + b0), gelu_new(a[1] + b1));
                *(__half2*)&Ch[(size_t)(r0g + 8) * N + c0g] =
                    __floats2half2_rn(gelu_new(a[2] + b0), gelu_new(a[3] + b1));
            } else {
                const int which = c0g / DM;
                const int h2    = (c0g % DM) >> 6;
                const int e0    = c0g & 63;
                const float sc  = (which == 0) ? 0.125f : 1.0f;
                __half* OP = (which == 0) ? Qp : ((which == 1) ? Kp : Vp);
                __half* p0 = OP + ((size_t)((r0g >> 10) * NH + h2)) * (SEQ * DH)
                               + (size_t)(r0g & (SEQ - 1)) * DH + e0;
                __half* p1 = OP + ((size_t)(((r0g + 8) >> 10) * NH + h2)) * (SEQ * DH)
                               + (size_t)((r0g + 8) & (SEQ - 1)) * DH + e0;
                *(__half2*)p0 = __floats2half2_rn((a[0] + b0) * sc, (a[1] + b1) * sc);
                *(__half2*)p1 = __floats2half2_rn((a[2] + b0) * sc, (a[3] + b1) * sc);
            }
        }
    }
}

// ---------------- merged prep + LN1 (one launch) --------------------------------
__device__ __forceinline__ void tr_tile(const float* __restrict__ in,
                                        __half* __restrict__ out,
                                        int C, int ldo, int c0, int r0,
                                        float* t, int tx, int ty)
{
    #pragma unroll
    for (int i = 0; i < 32; i += 8)
        t[(ty + i) * 33 + tx] = in[(size_t)(r0 + ty + i) * C + c0 + tx];
    __syncthreads();
    #pragma unroll
    for (int i = 0; i < 32; i += 8)
        out[(size_t)(c0 + ty + i) * ldo + r0 + tx] = __float2half(t[tx * 33 + ty + i]);
}

__device__ __forceinline__ void ln_row(const float* __restrict__ w,
                                       const float* __restrict__ b,
                                       __half* __restrict__ y, int t,
                                       float v0, float v1, float v2, float* sh)
{
    float s = v0 + v1 + v2;
    float q = v0 * v0 + v1 * v1 + v2 * v2;
    #pragma unroll
    for (int o = 16; o > 0; o >>= 1) {
        s += __shfl_xor_sync(0xffffffffu, s, o);
        q += __shfl_xor_sync(0xffffffffu, q, o);
    }
    const int lane = t & 31, wid = t >> 5;
    if (lane == 0) { sh[wid] = s; sh[wid + 8] = q; }
    __syncthreads();
    if (t == 0) {
        float ss = 0.f, qq = 0.f;
        #pragma unroll
        for (int i = 0; i < 8; i++) { ss += sh[i]; qq += sh[i + 8]; }
        sh[0] = ss; sh[8] = qq;
    }
    __syncthreads();
    s = sh[0]; q = sh[8];
    const float mu  = s * (1.0f / DM);
    const float inv = rsqrtf(q * (1.0f / DM) - mu * mu + 1e-5f);
    y[t]       = __float2half((v0 - mu) * inv * w[t]       + b[t]);
    y[t + 256] = __float2half((v1 - mu) * inv * w[t + 256] + b[t + 256]);
    y[t + 512] = __float2half((v2 - mu) * inv * w[t + 512] + b[t + 512]);
}

__global__ void __launch_bounds__(256) prep_ln1(
    const float* __restrict__ WQ, const float* __restrict__ WK, const float* __restrict__ WV,
    const float* __restrict__ WO, const float* __restrict__ Win, const float* __restrict__ Wout,
    const float* __restrict__ bq, const float* __restrict__ bk, const float* __restrict__ bv,
    __half* __restrict__ WqkvT, __half* __restrict__ WoT,
    __half* __restrict__ WinT,  __half* __restrict__ WoutT,
    float* __restrict__ qkvb,
    const float* __restrict__ X, const float* __restrict__ ln1w,
    const float* __restrict__ ln1b, __half* __restrict__ n1h)
{
    __shared__ float t[32 * 33];
    const int bid = blockIdx.x;
    const int tid = threadIdx.x;
    const int tx = tid & 31, ty = tid >> 5;

    if (bid < 1728) {
        const int which = bid / 576;
        const int r = bid % 576;
        const int h = r / 48, u = r % 48;
        const int c0 = (u & 1) * 32, r0 = (u >> 1) * 32;
        const float* in = ((which == 0) ? WQ : (which == 1) ? WK : WV) + (size_t)h * DM * DH;
        __half* out = WqkvT + (size_t)which * DM * DM + (size_t)h * DH * DM;
        tr_tile(in, out, DH, DM, c0, r0, t, tx, ty);
    } else if (bid < 2304) {
        const int r = bid - 1728;
        const int h = r / 48, u = r % 48;
        const int c0 = (u % 24) * 32, r0 = (u / 24) * 32;
        tr_tile(WO + (size_t)h * DH * DM, WoT + h * DH, DM, DM, c0, r0, t, tx, ty);
    } else if (bid < 4608) {
        const int r = bid - 2304;
        const int c0 = (r % 96) * 32, r0 = (r / 96) * 32;
        tr_tile(Win, WinT, DMLP, DM, c0, r0, t, tx, ty);
    } else if (bid < 6912) {
        const int r = bid - 4608;
        const int c0 = (r % 24) * 32, r0 = (r / 24) * 32;
        tr_tile(Wout, WoutT, DM, DMLP, c0, r0, t, tx, ty);
    } else if (bid < 6921) {
        const int n = (bid - 6912) * 256 + tid;
        if (n < 3 * DM) {
            const float* s = (n < DM) ? bq : ((n < 2 * DM) ? bk : bv);
            qkvb[n] = s[n % DM];
        }
    } else {
        const int row = bid - 6921;
        const float* x = X + (size_t)row * DM;
        ln_row(ln1w, ln1b, n1h + (size_t)row * DM, tid,
               x[tid], x[tid + 256], x[tid + 512], t);
    }
}

// ---------------- LayerNorm (fp32 in -> fp16 out), LN2 ---------------------------
__global__ void __launch_bounds__(256) ln_kernel(
    const float* __restrict__ X, const float* __restrict__ w,
    const float* __restrict__ b, __half* __restrict__ Y)
{
    __shared__ float sh[16];
    const int row = blockIdx.x;
    const float* x = X + (size_t)row * DM;
    const int t = threadIdx.x;
    ln_row(w, b, Y + (size_t)row * DM, t, x[t], x[t + 256], x[t + 512], sh);
}

// ---------------- tensor-core causal flash attention (round-5 best) -------------
#define ALD 72
#define ATTN_SMEM ((64 + 128 + 128) * ALD * 2)
#define L2E 1.4426950408889634f

__global__ void __launch_bounds__(128) attn_mma(
    const __half* __restrict__ Q, const __half* __restrict__ K,
    const __half* __restrict__ V, __half* __restrict__ Z)
{
    extern __shared__ __half as_[];
    __half* Qs = as_;
    __half* Ks = as_ + 64 * ALD;
    __half* Vs = as_ + (64 + 128) * ALD;

    const int tid  = threadIdx.x;
    const int lane = tid & 31;
    const int w    = tid >> 5;
    const int bh   = blockIdx.y;
    const int q0   = (15 - blockIdx.x) * 64;
    const int nt   = q0 / 64 + 1;

    const __half* Qb = Q + (size_t)bh * (SEQ * DH);
    const __half* Kb = K + (size_t)bh * (SEQ * DH);
    const __half* Vb = V + (size_t)bh * (SEQ * DH);

    const uint32_t sQ = smem_u32(Qs);
    const uint32_t sK = smem_u32(Ks);
    const uint32_t sV = smem_u32(Vs);

    #pragma unroll
    for (int i = 0; i < 4; i++) {
        int c = tid + i * 128;
        int row = c >> 3, col = (c & 7) * 8;
        *(float4*)&Qs[row * ALD + col] = *(const float4*)&Qb[(size_t)(q0 + row) * DH + col];
    }

    auto load_kv = [&](int kt, int buf) {
        const int k0 = kt * 64;
        const uint32_t bK_ = sK + (uint32_t)buf * (64 * ALD * 2);
        const uint32_t bV_ = sV + (uint32_t)buf * (64 * ALD * 2);
        #pragma unroll
        for (int i = 0; i < 4; i++) {
            int c = tid + i * 128;
            int row = c >> 3, col = (c & 7) * 8;
            cpasync16(bK_ + (uint32_t)(row * ALD + col) * 2,
                      Kb + (size_t)(k0 + row) * DH + col);
            cpasync16(bV_ + (uint32_t)(row * ALD + col) * 2,
                      Vb + (size_t)(k0 + row) * DH + col);
        }
    };

    load_kv(0, 0); CP_COMMIT();
    __syncthreads();

    uint32_t qf[4][4];
    {
        const uint32_t qoff = sQ + (uint32_t)((w * 16 + (lane & 15)) * ALD + (lane >> 4) * 8) * 2;
        #pragma unroll
        for (int ks = 0; ks < 4; ks++)
            ldsm4(qf[ks][0], qf[ks][1], qf[ks][2], qf[ks][3], qoff + ks * 32);
    }

    float o[8][4];
    #pragma unroll
    for (int j = 0; j < 8; j++)
        #pragma unroll
        for (int x = 0; x < 4; x++) o[j][x] = 0.0f;
    float m0 = -1e30f, m1 = -1e30f, l0 = 0.0f, l1 = 0.0f;

    const uint32_t koff = (uint32_t)(((lane >> 4) * 8 + (lane & 7)) * ALD + ((lane >> 3) & 1) * 8) * 2;
    const uint32_t voff = (uint32_t)(((lane & 7) + ((lane >> 3) & 1) * 8) * ALD + (lane >> 4) * 8) * 2;
    const int grow = lane >> 2, gcol = (lane & 3) * 2;

    for (int kt = 0; kt < nt; kt++) {
        const int buf = kt & 1;
        if (kt + 1 < nt) { load_kv(kt + 1, buf ^ 1); CP_COMMIT(); CP_WAIT1(); }
        else            { CP_WAIT0(); }
        __syncthreads();

        const uint32_t bK_ = sK + (uint32_t)buf * (64 * ALD * 2);
        const uint32_t bV_ = sV + (uint32_t)buf * (64 * ALD * 2);

        float c_[8][4];
        #pragma unroll
        for (int j = 0; j < 8; j++)
            #pragma unroll
            for (int x = 0; x < 4; x++) c_[j][x] = 0.0f;
        #pragma unroll
        for (int ks = 0; ks < 4; ks++) {
            #pragma unroll
            for (int j2 = 0; j2 < 4; j2++) {
                uint32_t b0, b1, b2, b3;
                ldsm4(b0, b1, b2, b3, bK_ + koff + (uint32_t)(j2 * 16 * ALD + ks * 16) * 2);
                mma16816(c_[2 * j2],     qf[ks][0], qf[ks][1], qf[ks][2], qf[ks][3], b0, b1);
                mma16816(c_[2 * j2 + 1], qf[ks][0], qf[ks][1], qf[ks][2], qf[ks][3], b2, b3);
            }
        }

        if (kt == nt - 1) {
            const int row0 = q0 + w * 16 + grow;
            const int k0   = kt * 64;
            #pragma unroll
            for (int j = 0; j < 8; j++) {
                const int col = k0 + j * 8 + gcol;
                if (col     > row0)     c_[j][0] = -1e30f;
                if (col + 1 > row0)     c_[j][1] = -1e30f;
                if (col     > row0 + 8) c_[j][2] = -1e30f;
                if (col + 1 > row0 + 8) c_[j][3] = -1e30f;
            }
        }

        float tm0 = -1e30f, tm1 = -1e30f;
        #pragma unroll
        for (int j = 0; j < 8; j++) {
            tm0 = fmaxf(tm0, fmaxf(c_[j][0], c_[j][1]));
            tm1 = fmaxf(tm1, fmaxf(c_[j][2], c_[j][3]));
        }
        tm0 = fmaxf(tm0, __shfl_xor_sync(0xffffffffu, tm0, 1));
        tm0 = fmaxf(tm0, __shfl_xor_sync(0xffffffffu, tm0, 2));
        tm1 = fmaxf(tm1, __shfl_xor_sync(0xffffffffu, tm1, 1));
        tm1 = fmaxf(tm1, __shfl_xor_sync(0xffffffffu, tm1, 2));
        const float mn0 = fmaxf(m0, tm0), mn1 = fmaxf(m1, tm1);
        const float corr0 = exp2_poly((m0 - mn0) * L2E);
        const float corr1 = exp2_poly((m1 - mn1) * L2E);
        m0 = mn0; m1 = mn1;

        uint32_t ph[8][2];
        float s0 = 0.0f, s1 = 0.0f;
        #pragma unroll
        for (int j = 0; j < 8; j++) {
            ph[j][0] = exp2_h2((c_[j][0] - mn0) * L2E, (c_[j][1] - mn0) * L2E);
            float2 p0 = __half22float2(*(__half2*)&ph[j][0]);
            s0 += p0.x + p0.y;
            const float e2 = exp2_poly((c_[j][2] - mn1) * L2E);
            const float e3 = exp2_poly((c_[j][3] - mn1) * L2E);
            __half2 hh2 = __floats2half2_rn(e2, e3);
            ph[j][1] = *(uint32_t*)&hh2;
            s1 += e2 + e3;
        }
        s0 += __shfl_xor_sync(0xffffffffu, s0, 1);
        s0 += __shfl_xor_sync(0xffffffffu, s0, 2);
        s1 += __shfl_xor_sync(0xffffffffu, s1, 1);
        s1 += __shfl_xor_sync(0xffffffffu, s1, 2);
        l0 = l0 * corr0 + s0;
        l1 = l1 * corr1 + s1;
        #pragma unroll
        for (int j = 0; j < 8; j++) {
            o[j][0] *= corr0; o[j][1] *= corr0;
            o[j][2] *= corr1; o[j][3] *= corr1;
        }

        #pragma unroll
        for (int ks = 0; ks < 4; ks++) {
            const uint32_t a0 = ph[2 * ks][0],     a1 = ph[2 * ks][1];
            const uint32_t a2 = ph[2 * ks + 1][0], a3 = ph[2 * ks + 1][1];
            #pragma unroll
            for (int j2 = 0; j2 < 4; j2++) {
                uint32_t b0, b1, b2, b3;
                ldsm4t(b0, b1, b2, b3, bV_ + voff + (uint32_t)(ks * 16 * ALD + j2 * 16) * 2);
                mma16816(o[2 * j2],     a0, a1, a2, a3, b0, b1);
                mma16816(o[2 * j2 + 1], a0, a1, a2, a3, b2, b3);
            }
        }
        __syncthreads();
    }

    const int b = bh / NH, h = bh % NH;
    const float i0 = __fdividef(1.0f, l0), i1 = __fdividef(1.0f, l1);
    const int row0 = q0 + w * 16 + grow;
    const size_t t0 = (size_t)b * SEQ + row0;
    const size_t t1 = t0 + 8;
    #pragma unroll
    for (int j = 0; j < 8; j++) {
        const int col = h * DH + j * 8 + gcol;
        *(__half2*)&Z[t0 * DM + col] = __floats2half2_rn(o[j][0] * i0, o[j][1] * i0);
        *(__half2*)&Z[t1 * DM + col] = __floats2half2_rn(o[j][2] * i1, o[j][3] * i1);
    }
}

// ---------------- launch --------------------------------------------------------
extern "C" void kernel_launch(void* const* d_in, const int* in_sizes, int n_in,
                              void* d_out, int out_size) {
    const float* resid_pre = (const float*)d_in[0];
    const float* W_Q  = (const float*)d_in[1];
    const float* b_Q  = (const float*)d_in[2];
    const float* W_K  = (const float*)d_in[3];
    const float* b_K  = (const float*)d_in[4];
    const float* W_V  = (const float*)d_in[5];
    const float* b_V  = (const float*)d_in[6];
    const float* W_O  = (const float*)d_in[7];
    const float* b_O  = (const float*)d_in[8];
    const float* ln1w = (const float*)d_in[9];
    const float* ln1b = (const float*)d_in[10];
    const float* ln2w = (const float*)d_in[11];
    const float* ln2b = (const float*)d_in[12];
    const float* W_in = (const float*)d_in[13];
    const float* b_in = (const float*)d_in[14];
    const float* W_out= (const float*)d_in[15];
    const float* b_out= (const float*)d_in[16];
    float* out = (float*)d_out;

    __half *n1h, *zh, *n2h, *hh, *WqkvT, *WoT, *WinT, *WoutT, *q, *k, *v;
    float *rm, *qkvb;
    cudaGetSymbolAddress((void**)&n1h,  g_n1h);
    cudaGetSymbolAddress((void**)&q,    g_q);
    cudaGetSymbolAddress((void**)&k,    g_k);
    cudaGetSymbolAddress((void**)&v,    g_v);
    cudaGetSymbolAddress((void**)&zh,   g_zh);
    cudaGetSymbolAddress((void**)&rm,   g_rm);
    cudaGetSymbolAddress((void**)&n2h,  g_n2h);
    cudaGetSymbolAddress((void**)&hh,   g_hh);
    cudaGetSymbolAddress((void**)&WqkvT,g_WqkvT);
    cudaGetSymbolAddress((void**)&WoT,  g_WoT);
    cudaGetSymbolAddress((void**)&WinT, g_WinT);
    cudaGetSymbolAddress((void**)&WoutT,g_WoutT);
    cudaGetSymbolAddress((void**)&qkvb, g_qkvb);

    cudaFuncSetAttribute((const void*)mma_gemm<0>, cudaFuncAttributeMaxDynamicSharedMemorySize, GEMM_SMEM);
    cudaFuncSetAttribute((const void*)mma_gemm<1>, cudaFuncAttributeMaxDynamicSharedMemorySize, GEMM_SMEM);
    cudaFuncSetAttribute((const void*)mma_gemm<2>, cudaFuncAttributeMaxDynamicSharedMemorySize, GEMM_SMEM);
    cudaFuncSetAttribute((const void*)attn_mma,    cudaFuncAttributeMaxDynamicSharedMemorySize, ATTN_SMEM);

    // merged prep + LN1
    prep_ln1<<<6921 + TOK, 256>>>(W_Q, W_K, W_V, W_O, W_in, W_out,
                                  b_Q, b_K, b_V,
                                  WqkvT, WoT, WinT, WoutT, qkvb,
                                  resid_pre, ln1w, ln1b, n1h);

    mma_gemm<2><<<dim3(18, 64), 256, GEMM_SMEM>>>(n1h, WqkvT, qkvb, nullptr,
                                                  nullptr, nullptr, q, k, v, 3*DM, DM);
    attn_mma<<<dim3(16, 96), 128, ATTN_SMEM>>>(q, k, v, zh);
    mma_gemm<0><<<dim3(6, 64), 256, GEMM_SMEM>>>(zh, WoT, b_O, resid_pre,
                                                 rm, nullptr, nullptr, nullptr, nullptr, DM, DM);
    ln_kernel<<<TOK, 256>>>(rm, ln2w, ln2b, n2h);
    mma_gemm<1><<<dim3(24, 64), 256, GEMM_SMEM>>>(n2h, WinT, b_in, nullptr,
                                                  nullptr, hh, nullptr, nullptr, nullptr, DMLP, DM);
    mma_gemm<0><<<dim3(6, 64), 256, GEMM_SMEM>>>(hh, WoutT, b_out, rm,
                                                 out, nullptr, nullptr, nullptr, nullptr, DM, DMLP);
}

// round 16
// speedup vs baseline: 1.0600x; 1.0156x over previous
#include <cuda_runtime.h>
#include <cuda_fp16.h>
#include <cstdint>

#define TOK 8192
#define SEQ 1024
#define DM  768
#define NH  12
#define DH  64
#define DMLP 3072

// ---------------- scratch ----------------------------------------------------
__device__ __half g_n1h[TOK*DM];
__device__ __half g_q [TOK*DM];
__device__ __half g_k [TOK*DM];
__device__ __half g_v [TOK*DM];
__device__ __half g_zh[TOK*DM];
__device__ float  g_rm[TOK*DM];
__device__ __half g_n2h[TOK*DM];
__device__ __half g_hh[TOK*DMLP];
__device__ __half g_WqkvT[3*DM*DM];
__device__ __half g_WoT  [DM*DM];
__device__ __half g_WinT [DMLP*DM];
__device__ __half g_WoutT[DM*DMLP];
__device__ float  g_qkvb[3*DM];

typedef unsigned long long u64;

// gelu with hardware tanh approximation (MUFU, single op)
__device__ __forceinline__ float gelu_new(float x) {
    float x3 = x * x * x;
    float a  = 0.7978845608028654f * (x + 0.044715f * x3);
    float t;
    asm("tanh.approx.f32 %0, %1;" : "=f"(t) : "f"(a));
    return 0.5f * x * (1.0f + t);
}

// ---------------- mma / ldmatrix / cp.async helpers ----------------------------
__device__ __forceinline__ uint32_t smem_u32(const void* p) {
    uint32_t a;
    asm("{ .reg .u64 t; cvta.to.shared.u64 t, %1; cvt.u32.u64 %0, t; }" : "=r"(a) : "l"(p));
    return a;
}
__device__ __forceinline__ void cpasync16(uint32_t dst, const void* src) {
    asm volatile("cp.async.cg.shared.global [%0], [%1], 16;" :: "r"(dst), "l"(src));
}
#define CP_COMMIT() asm volatile("cp.async.commit_group;" ::: "memory")
#define CP_WAIT1()  asm volatile("cp.async.wait_group 1;" ::: "memory")
#define CP_WAIT0()  asm volatile("cp.async.wait_group 0;" ::: "memory")

__device__ __forceinline__ void ldsm4(uint32_t &r0, uint32_t &r1, uint32_t &r2, uint32_t &r3,
                                      uint32_t addr) {
    asm volatile("ldmatrix.sync.aligned.m8n8.x4.shared.b16 {%0,%1,%2,%3}, [%4];"
                 : "=r"(r0), "=r"(r1), "=r"(r2), "=r"(r3) : "r"(addr));
}
__device__ __forceinline__ void ldsm4t(uint32_t &r0, uint32_t &r1, uint32_t &r2, uint32_t &r3,
                                       uint32_t addr) {
    asm volatile("ldmatrix.sync.aligned.m8n8.x4.trans.shared.b16 {%0,%1,%2,%3}, [%4];"
                 : "=r"(r0), "=r"(r1), "=r"(r2), "=r"(r3) : "r"(addr));
}
__device__ __forceinline__ void mma16816(float* c, uint32_t a0, uint32_t a1, uint32_t a2,
                                         uint32_t a3, uint32_t b0, uint32_t b1) {
    asm volatile("mma.sync.aligned.m16n8k16.row.col.f32.f16.f16.f32 "
                 "{%0,%1,%2,%3},{%4,%5,%6,%7},{%8,%9},{%0,%1,%2,%3};"
                 : "+f"(c[0]), "+f"(c[1]), "+f"(c[2]), "+f"(c[3])
                 : "r"(a0), "r"(a1), "r"(a2), "r"(a3), "r"(b0), "r"(b1));
}
__device__ __forceinline__ uint32_t exp2_h2(float e0, float e1) {
    __half2 h = __floats2half2_rn(e0, e1);
    uint32_t hi = *(uint32_t*)&h, r;
    asm("ex2.approx.f16x2 %0, %1;" : "=r"(r) : "r"(hi));
    return r;
}
__device__ __forceinline__ float exp2_poly(float t) {
    t = fmaxf(t, -30.0f);
    const float z = t + 12582912.0f;
    const int   n = __float_as_int(z) << 23;
    const float f = t - (z - 12582912.0f);
    float p = 0.009618129f;
    p = fmaf(p, f, 0.05550411f);
    p = fmaf(p, f, 0.24022651f);
    p = fmaf(p, f, 0.69314718f);
    p = fmaf(p, f, 1.0f);
    return __int_as_float(__float_as_int(p) + n);
}

// ---------------- HMMA GEMM: BK=64, 3 stages, 8 warps, warp tile 64x32 ----------
#define LDSH 72
#define STG_H (2 * 128 * LDSH)
#define GEMM_SMEM (3 * STG_H * 2)        // 110592 B

template<int EPI>
__global__ void __launch_bounds__(256, 2) mma_gemm(
    const __half* __restrict__ A, const __half* __restrict__ Bt,
    const float* __restrict__ bias, const float* __restrict__ R,
    float* __restrict__ C, __half* __restrict__ Ch,
    __half* __restrict__ Qp, __half* __restrict__ Kp, __half* __restrict__ Vp,
    int N, int K)
{
    extern __shared__ __half sm[];
    const int tid  = threadIdx.x;
    const int lane = tid & 31, wid = tid >> 5;
    const int wm = wid >> 2, wn = wid & 3;
    const int col0 = blockIdx.x * 128;
    const int row0 = blockIdx.y * 128;
    const int KT = K / 64;

    const uint32_t sbase = smem_u32(sm);

    float acc[4][4][4];
    #pragma unroll
    for (int i = 0; i < 4; i++)
        #pragma unroll
        for (int j = 0; j < 4; j++)
            #pragma unroll
            for (int x = 0; x < 4; x++) acc[i][j][x] = 0.0f;

    auto load_stage = [&](int s, int kt) {
        const uint32_t st = sbase + (uint32_t)s * (STG_H * 2);
        const int kk = kt * 64;
        #pragma unroll
        for (int h = 0; h < 4; h++) {
            const int c  = tid + h * 256;
            const int r  = c >> 3;
            const int kc = (c & 7) * 8;
            cpasync16(st + (uint32_t)(r * LDSH + kc) * 2,
                      A + (size_t)(row0 + r) * K + kk + kc);
            cpasync16(st + (uint32_t)((128 + r) * LDSH + kc) * 2,
                      Bt + (size_t)(col0 + r) * K + kk + kc);
        }
    };

    auto compute_stage = [&](int s) {
        const uint32_t aB = sbase + (uint32_t)s * (STG_H * 2);
        const uint32_t bB = aB + 128 * LDSH * 2;
        const int lrow = lane & 15;
        const int lcol = (lane >> 4) * 8;
        #pragma unroll
        for (int ks = 0; ks < 4; ks++) {
            const int ko = ks * 16 + lcol;
            uint32_t af[4][4];
            #pragma unroll
            for (int i = 0; i < 4; i++) {
                const int row = wm * 64 + i * 16 + lrow;
                ldsm4(af[i][0], af[i][1], af[i][2], af[i][3],
                      aB + (uint32_t)(row * LDSH + ko) * 2);
            }
            uint32_t bf[2][4];
            #pragma unroll
            for (int j = 0; j < 2; j++) {
                const int row = wn * 32 + j * 16 + lrow;
                ldsm4(bf[j][0], bf[j][1], bf[j][2], bf[j][3],
                      bB + (uint32_t)(row * LDSH + ko) * 2);
            }
            #pragma unroll
            for (int i = 0; i < 4; i++)
                #pragma unroll
                for (int j = 0; j < 4; j++)
                    mma16816(acc[i][j], af[i][0], af[i][1], af[i][2], af[i][3],
                             bf[j >> 1][j & 1], bf[j >> 1][(j & 1) + 2]);
        }
    };

    load_stage(0, 0); CP_COMMIT();
    load_stage(1, 1); CP_COMMIT();

    int sidx = 0;
    for (int kt = 0; kt < KT; kt++) {
        CP_WAIT1();
        __syncthreads();
        if (kt + 2 < KT) {
            int ns = sidx + 2; if (ns >= 3) ns -= 3;
            load_stage(ns, kt + 2);
        }
        CP_COMMIT();
        compute_stage(sidx);
        if (++sidx == 3) sidx = 0;
    }

    const int g = lane >> 2, t4 = lane & 3;
    #pragma unroll
    for (int i = 0; i < 4; i++) {
        const int r0g = row0 + wm * 64 + i * 16 + g;
        #pragma unroll
        for (int j = 0; j < 4; j++) {
            const int c0g = col0 + wn * 32 + j * 8 + t4 * 2;
            const float2 bb = *(const float2*)&bias[c0g];
            float* a = acc[i][j];
            if (EPI == 0) {
                float2 rA = *(const float2*)&R[(size_t)r0g * N + c0g];
                float2 rB = *(const float2*)&R[(size_t)(r0g + 8) * N + c0g];
                *(float2*)&C[(size_t)r0g * N + c0g] =
                    make_float2(a[0] + bb.x + rA.x, a[1] + bb.y + rA.y);
                *(float2*)&C[(size_t)(r0g + 8) * N + c0g] =
                    make_float2(a[2] + bb.x + rB.x, a[3] + bb.y + rB.y);
            } else if (EPI == 1) {
                *(__half2*)&Ch[(size_t)r0g * N + c0g] =
                    __floats2half2_rn(gelu_new(a[0] + bb.x), gelu_new(a[1] + bb.y));
                *(__half2*)&Ch[(size_t)(r0g + 8) * N + c0g] =
                    __floats2half2_rn(gelu_new(a[2] + bb.x), gelu_new(a[3] + bb.y));
            } else {
                const int which = c0g / DM;
                const int h2    = (c0g % DM) >> 6;
                const int e0    = c0g & 63;
                const float sc  = (which == 0) ? 0.125f : 1.0f;
                __half* OP = (which == 0) ? Qp : ((which == 1) ? Kp : Vp);
                __half* p0 = OP + ((size_t)((r0g >> 10) * NH + h2)) * (SEQ * DH)
                               + (size_t)(r0g & (SEQ - 1)) * DH + e0;
                __half* p1 = OP + ((size_t)(((r0g + 8) >> 10) * NH + h2)) * (SEQ * DH)
                               + (size_t)((r0g + 8) & (SEQ - 1)) * DH + e0;
                *(__half2*)p0 = __floats2half2_rn((a[0] + bb.x) * sc, (a[1] + bb.y) * sc);
                *(__half2*)p1 = __floats2half2_rn((a[2] + bb.x) * sc, (a[3] + bb.y) * sc);
            }
        }
    }
}

// ---------------- merged prep + LN1 (one launch) --------------------------------
__device__ __forceinline__ void tr_tile(const float* __restrict__ in,
                                        __half* __restrict__ out,
                                        int C, int ldo, int c0, int r0,
                                        float* t, int tx, int ty)
{
    #pragma unroll
    for (int i = 0; i < 32; i += 8)
        t[(ty + i) * 33 + tx] = in[(size_t)(r0 + ty + i) * C + c0 + tx];
    __syncthreads();
    #pragma unroll
    for (int i = 0; i < 32; i += 8)
        out[(size_t)(c0 + ty + i) * ldo + r0 + tx] = __float2half(t[tx * 33 + ty + i]);
}

__device__ __forceinline__ void ln_row(const float* __restrict__ w,
                                       const float* __restrict__ b,
                                       __half* __restrict__ y, int t,
                                       float v0, float v1, float v2, float* sh)
{
    float s = v0 + v1 + v2;
    float q = v0 * v0 + v1 * v1 + v2 * v2;
    #pragma unroll
    for (int o = 16; o > 0; o >>= 1) {
        s += __shfl_xor_sync(0xffffffffu, s, o);
        q += __shfl_xor_sync(0xffffffffu, q, o);
    }
    const int lane = t & 31, wid = t >> 5;
    if (lane == 0) { sh[wid] = s; sh[wid + 8] = q; }
    __syncthreads();
    if (t == 0) {
        float ss = 0.f, qq = 0.f;
        #pragma unroll
        for (int i = 0; i < 8; i++) { ss += sh[i]; qq += sh[i + 8]; }
        sh[0] = ss; sh[8] = qq;
    }
    __syncthreads();
    s = sh[0]; q = sh[8];
    const float mu  = s * (1.0f / DM);
    const float inv = rsqrtf(q * (1.0f / DM) - mu * mu + 1e-5f);
    y[t]       = __float2half((v0 - mu) * inv * w[t]       + b[t]);
    y[t + 256] = __float2half((v1 - mu) * inv * w[t + 256] + b[t + 256]);
    y[t + 512] = __float2half((v2 - mu) * inv * w[t + 512] + b[t + 512]);
}

__global__ void __launch_bounds__(256) prep_ln1(
    const float* __restrict__ WQ, const float* __restrict__ WK, const float* __restrict__ WV,
    const float* __restrict__ WO, const float* __restrict__ Win, const float* __restrict__ Wout,
    const float* __restrict__ bq, const float* __restrict__ bk, const float* __restrict__ bv,
    __half* __restrict__ WqkvT, __half* __restrict__ WoT,
    __half* __restrict__ WinT,  __half* __restrict__ WoutT,
    float* __restrict__ qkvb,
    const float* __restrict__ X, const float* __restrict__ ln1w,
    const float* __restrict__ ln1b, __half* __restrict__ n1h)
{
    __shared__ float t[32 * 33];
    const int bid = blockIdx.x;
    const int tid = threadIdx.x;
    const int tx = tid & 31, ty = tid >> 5;

    if (bid < 1728) {
        const int which = bid / 576;
        const int r = bid % 576;
        const int h = r / 48, u = r % 48;
        const int c0 = (u & 1) * 32, r0 = (u >> 1) * 32;
        const float* in = ((which == 0) ? WQ : (which == 1) ? WK : WV) + (size_t)h * DM * DH;
        __half* out = WqkvT + (size_t)which * DM * DM + (size_t)h * DH * DM;
        tr_tile(in, out, DH, DM, c0, r0, t, tx, ty);
    } else if (bid < 2304) {
        const int r = bid - 1728;
        const int h = r / 48, u = r % 48;
        const int c0 = (u % 24) * 32, r0 = (u / 24) * 32;
        tr_tile(WO + (size_t)h * DH * DM, WoT + h * DH, DM, DM, c0, r0, t, tx, ty);
    } else if (bid < 4608) {
        const int r = bid - 2304;
        const int c0 = (r % 96) * 32, r0 = (r / 96) * 32;
        tr_tile(Win, WinT, DMLP, DM, c0, r0, t, tx, ty);
    } else if (bid < 6912) {
        const int r = bid - 4608;
        const int c0 = (r % 24) * 32, r0 = (r / 24) * 32;
        tr_tile(Wout, WoutT, DM, DMLP, c0, r0, t, tx, ty);
    } else if (bid < 6921) {
        const int n = (bid - 6912) * 256 + tid;
        if (n < 3 * DM) {
            const float* s = (n < DM) ? bq : ((n < 2 * DM) ? bk : bv);
            qkvb[n] = s[n % DM];
        }
    } else {
        const int row = bid - 6921;
        const float* x = X + (size_t)row * DM;
        ln_row(ln1w, ln1b, n1h + (size_t)row * DM, tid,
               x[tid], x[tid + 256], x[tid + 512], t);
    }
}

// ---------------- LayerNorm (fp32 in -> fp16 out), LN2 ---------------------------
__global__ void __launch_bounds__(256) ln_kernel(
    const float* __restrict__ X, const float* __restrict__ w,
    const float* __restrict__ b, __half* __restrict__ Y)
{
    __shared__ float sh[16];
    const int row = blockIdx.x;
    const float* x = X + (size_t)row * DM;
    const int t = threadIdx.x;
    ln_row(w, b, Y + (size_t)row * DM, t, x[t], x[t + 256], x[t + 512], sh);
}

// ---------------- tensor-core causal flash attention (round-5 best) -------------
#define ALD 72
#define ATTN_SMEM ((64 + 128 + 128) * ALD * 2)
#define L2E 1.4426950408889634f

__global__ void __launch_bounds__(128) attn_mma(
    const __half* __restrict__ Q, const __half* __restrict__ K,
    const __half* __restrict__ V, __half* __restrict__ Z)
{
    extern __shared__ __half as_[];
    __half* Qs = as_;
    __half* Ks = as_ + 64 * ALD;
    __half* Vs = as_ + (64 + 128) * ALD;

    const int tid  = threadIdx.x;
    const int lane = tid & 31;
    const int w    = tid >> 5;
    const int bh   = blockIdx.y;
    const int q0   = (15 - blockIdx.x) * 64;
    const int nt   = q0 / 64 + 1;

    const __half* Qb = Q + (size_t)bh * (SEQ * DH);
    const __half* Kb = K + (size_t)bh * (SEQ * DH);
    const __half* Vb = V + (size_t)bh * (SEQ * DH);

    const uint32_t sQ = smem_u32(Qs);
    const uint32_t sK = smem_u32(Ks);
    const uint32_t sV = smem_u32(Vs);

    #pragma unroll
    for (int i = 0; i < 4; i++) {
        int c = tid + i * 128;
        int row = c >> 3, col = (c & 7) * 8;
        *(float4*)&Qs[row * ALD + col] = *(const float4*)&Qb[(size_t)(q0 + row) * DH + col];
    }

    auto load_kv = [&](int kt, int buf) {
        const int k0 = kt * 64;
        const uint32_t bK_ = sK + (uint32_t)buf * (64 * ALD * 2);
        const uint32_t bV_ = sV + (uint32_t)buf * (64 * ALD * 2);
        #pragma unroll
        for (int i = 0; i < 4; i++) {
            int c = tid + i * 128;
            int row = c >> 3, col = (c & 7) * 8;
            cpasync16(bK_ + (uint32_t)(row * ALD + col) * 2,
                      Kb + (size_t)(k0 + row) * DH + col);
            cpasync16(bV_ + (uint32_t)(row * ALD + col) * 2,
                      Vb + (size_t)(k0 + row) * DH + col);
        }
    };

    load_kv(0, 0); CP_COMMIT();
    __syncthreads();

    uint32_t qf[4][4];
    {
        const uint32_t qoff = sQ + (uint32_t)((w * 16 + (lane & 15)) * ALD + (lane >> 4) * 8) * 2;
        #pragma unroll
        for (int ks = 0; ks < 4; ks++)
            ldsm4(qf[ks][0], qf[ks][1], qf[ks][2], qf[ks][3], qoff + ks * 32);
    }

    float o[8][4];
    #pragma unroll
    for (int j = 0; j < 8; j++)
        #pragma unroll
        for (int x = 0; x < 4; x++) o[j][x] = 0.0f;
    float m0 = -1e30f, m1 = -1e30f, l0 = 0.0f, l1 = 0.0f;

    const uint32_t koff = (uint32_t)(((lane >> 4) * 8 + (lane & 7)) * ALD + ((lane >> 3) & 1) * 8) * 2;
    const uint32_t voff = (uint32_t)(((lane & 7) + ((lane >> 3) & 1) * 8) * ALD + (lane >> 4) * 8) * 2;
    const int grow = lane >> 2, gcol = (lane & 3) * 2;

    for (int kt = 0; kt < nt; kt++) {
        const int buf = kt & 1;
        if (kt + 1 < nt) { load_kv(kt + 1, buf ^ 1); CP_COMMIT(); CP_WAIT1(); }
        else            { CP_WAIT0(); }
        __syncthreads();

        const uint32_t bK_ = sK + (uint32_t)buf * (64 * ALD * 2);
        const uint32_t bV_ = sV + (uint32_t)buf * (64 * ALD * 2);

        float c_[8][4];
        #pragma unroll
        for (int j = 0; j < 8; j++)
            #pragma unroll
            for (int x = 0; x < 4; x++) c_[j][x] = 0.0f;
        #pragma unroll
        for (int ks = 0; ks < 4; ks++) {
            #pragma unroll
            for (int j2 = 0; j2 < 4; j2++) {
                uint32_t b0, b1, b2, b3;
                ldsm4(b0, b1, b2, b3, bK_ + koff + (uint32_t)(j2 * 16 * ALD + ks * 16) * 2);
                mma16816(c_[2 * j2],     qf[ks][0], qf[ks][1], qf[ks][2], qf[ks][3], b0, b1);
                mma16816(c_[2 * j2 + 1], qf[ks][0], qf[ks][1], qf[ks][2], qf[ks][3], b2, b3);
            }
        }

        if (kt == nt - 1) {
            const int row0 = q0 + w * 16 + grow;
            const int k0   = kt * 64;
            #pragma unroll
            for (int j = 0; j < 8; j++) {
                const int col = k0 + j * 8 + gcol;
                if (col     > row0)     c_[j][0] = -1e30f;
                if (col + 1 > row0)     c_[j][1] = -1e30f;
                if (col     > row0 + 8) c_[j][2] = -1e30f;
                if (col + 1 > row0 + 8) c_[j][3] = -1e30f;
            }
        }

        float tm0 = -1e30f, tm1 = -1e30f;
        #pragma unroll
        for (int j = 0; j < 8; j++) {
            tm0 = fmaxf(tm0, fmaxf(c_[j][0], c_[j][1]));
            tm1 = fmaxf(tm1, fmaxf(c_[j][2], c_[j][3]));
        }
        tm0 = fmaxf(tm0, __shfl_xor_sync(0xffffffffu, tm0, 1));
        tm0 = fmaxf(tm0, __shfl_xor_sync(0xffffffffu, tm0, 2));
        tm1 = fmaxf(tm1, __shfl_xor_sync(0xffffffffu, tm1, 1));
        tm1 = fmaxf(tm1, __shfl_xor_sync(0xffffffffu, tm1, 2));
        const float mn0 = fmaxf(m0, tm0), mn1 = fmaxf(m1, tm1);
        const float corr0 = exp2_poly((m0 - mn0) * L2E);
        const float corr1 = exp2_poly((m1 - mn1) * L2E);
        m0 = mn0; m1 = mn1;

        uint32_t ph[8][2];
        float s0 = 0.0f, s1 = 0.0f;
        #pragma unroll
        for (int j = 0; j < 8; j++) {
            ph[j][0] = exp2_h2((c_[j][0] - mn0) * L2E, (c_[j][1] - mn0) * L2E);
            float2 p0 = __half22float2(*(__half2*)&ph[j][0]);
            s0 += p0.x + p0.y;
            const float e2 = exp2_poly((c_[j][2] - mn1) * L2E);
            const float e3 = exp2_poly((c_[j][3] - mn1) * L2E);
            __half2 hh2 = __floats2half2_rn(e2, e3);
            ph[j][1] = *(uint32_t*)&hh2;
            s1 += e2 + e3;
        }
        s0 += __shfl_xor_sync(0xffffffffu, s0, 1);
        s0 += __shfl_xor_sync(0xffffffffu, s0, 2);
        s1 += __shfl_xor_sync(0xffffffffu, s1, 1);
        s1 += __shfl_xor_sync(0xffffffffu, s1, 2);
        l0 = l0 * corr0 + s0;
        l1 = l1 * corr1 + s1;
        #pragma unroll
        for (int j = 0; j < 8; j++) {
            o[j][0] *= corr0; o[j][1] *= corr0;
            o[j][2] *= corr1; o[j][3] *= corr1;
        }

        #pragma unroll
        for (int ks = 0; ks < 4; ks++) {
            const uint32_t a0 = ph[2 * ks][0],     a1 = ph[2 * ks][1];
            const uint32_t a2 = ph[2 * ks + 1][0], a3 = ph[2 * ks + 1][1];
            #pragma unroll
            for (int j2 = 0; j2 < 4; j2++) {
                uint32_t b0, b1, b2, b3;
                ldsm4t(b0, b1, b2, b3, bV_ + voff + (uint32_t)(ks * 16 * ALD + j2 * 16) * 2);
                mma16816(o[2 * j2],     a0, a1, a2, a3, b0, b1);
                mma16816(o[2 * j2 + 1], a0, a1, a2, a3, b2, b3);
            }
        }
        __syncthreads();
    }

    const int b = bh / NH, h = bh % NH;
    const float i0 = __fdividef(1.0f, l0), i1 = __fdividef(1.0f, l1);
    const int row0 = q0 + w * 16 + grow;
    const size_t t0 = (size_t)b * SEQ + row0;
    const size_t t1 = t0 + 8;
    #pragma unroll
    for (int j = 0; j < 8; j++) {
        const int col = h * DH + j * 8 + gcol;
        *(__half2*)&Z[t0 * DM + col] = __floats2half2_rn(o[j][0] * i0, o[j][1] * i0);
        *(__half2*)&Z[t1 * DM + col] = __floats2half2_rn(o[j][2] * i1, o[j][3] * i1);
    }
}

// ---------------- launch --------------------------------------------------------
extern "C" void kernel_launch(void* const* d_in, const int* in_sizes, int n_in,
                              void* d_out, int out_size) {
    const float* resid_pre = (const float*)d_in[0];
    const float* W_Q  = (const float*)d_in[1];
    const float* b_Q  = (const float*)d_in[2];
    const float* W_K  = (const float*)d_in[3];
    const float* b_K  = (const float*)d_in[4];
    const float* W_V  = (const float*)d_in[5];
    const float* b_V  = (const float*)d_in[6];
    const float* W_O  = (const float*)d_in[7];
    const float* b_O  = (const float*)d_in[8];
    const float* ln1w = (const float*)d_in[9];
    const float* ln1b = (const float*)d_in[10];
    const float* ln2w = (const float*)d_in[11];
    const float* ln2b = (const float*)d_in[12];
    const float* W_in = (const float*)d_in[13];
    const float* b_in = (const float*)d_in[14];
    const float* W_out= (const float*)d_in[15];
    const float* b_out= (const float*)d_in[16];
    float* out = (float*)d_out;

    __half *n1h, *zh, *n2h, *hh, *WqkvT, *WoT, *WinT, *WoutT, *q, *k, *v;
    float *rm, *qkvb;
    cudaGetSymbolAddress((void**)&n1h,  g_n1h);
    cudaGetSymbolAddress((void**)&q,    g_q);
    cudaGetSymbolAddress((void**)&k,    g_k);
    cudaGetSymbolAddress((void**)&v,    g_v);
    cudaGetSymbolAddress((void**)&zh,   g_zh);
    cudaGetSymbolAddress((void**)&rm,   g_rm);
    cudaGetSymbolAddress((void**)&n2h,  g_n2h);
    cudaGetSymbolAddress((void**)&hh,   g_hh);
    cudaGetSymbolAddress((void**)&WqkvT,g_WqkvT);
    cudaGetSymbolAddress((void**)&WoT,  g_WoT);
    cudaGetSymbolAddress((void**)&WinT, g_WinT);
    cudaGetSymbolAddress((void**)&WoutT,g_WoutT);
    cudaGetSymbolAddress((void**)&qkvb, g_qkvb);

    cudaFuncSetAttribute((const void*)mma_gemm<0>, cudaFuncAttributeMaxDynamicSharedMemorySize, GEMM_SMEM);
    cudaFuncSetAttribute((const void*)mma_gemm<1>, cudaFuncAttributeMaxDynamicSharedMemorySize, GEMM_SMEM);
    cudaFuncSetAttribute((const void*)mma_gemm<2>, cudaFuncAttributeMaxDynamicSharedMemorySize, GEMM_SMEM);
    cudaFuncSetAttribute((const void*)attn_mma,    cudaFuncAttributeMaxDynamicSharedMemorySize, ATTN_SMEM);

    prep_ln1<<<6921 + TOK, 256>>>(W_Q, W_K, W_V, W_O, W_in, W_out,
                                  b_Q, b_K, b_V,
                                  WqkvT, WoT, WinT, WoutT, qkvb,
                                  resid_pre, ln1w, ln1b, n1h);

    mma_gemm<2><<<dim3(18, 64), 256, GEMM_SMEM>>>(n1h, WqkvT, qkvb, nullptr,
                                                  nullptr, nullptr, q, k, v, 3*DM, DM);
    attn_mma<<<dim3(16, 96), 128, ATTN_SMEM>>>(q, k, v, zh);
    mma_gemm<0><<<dim3(6, 64), 256, GEMM_SMEM>>>(zh, WoT, b_O, resid_pre,
                                                 rm, nullptr, nullptr, nullptr, nullptr, DM, DM);
    ln_kernel<<<TOK, 256>>>(rm, ln2w, ln2b, n2h);
    mma_gemm<1><<<dim3(24, 64), 256, GEMM_SMEM>>>(n2h, WinT, b_in, nullptr,
                                                  nullptr, hh, nullptr, nullptr, nullptr, DMLP, DM);
    mma_gemm<0><<<dim3(6, 64), 256, GEMM_SMEM>>>(hh, WoutT, b_out, rm,
                                                 out, nullptr, nullptr, nullptr, nullptr, DM, DMLP);
}

// round 17
// speedup vs baseline: 1.1043x; 1.0418x over previous
#include <cuda_runtime.h>
#include <cuda_fp16.h>
#include <cstdint>

#define TOK 8192
#define SEQ 1024
#define DM  768
#define NH  12
#define DH  64
#define DMLP 3072

// ---------------- scratch ----------------------------------------------------
__device__ __half g_n1h[TOK*DM];
__device__ __half g_q [TOK*DM];
__device__ __half g_k [TOK*DM];
__device__ __half g_v [TOK*DM];
__device__ __half g_zh[TOK*DM];
__device__ float  g_rm[TOK*DM];
__device__ __half g_n2h[TOK*DM];
__device__ __half g_hh[TOK*DMLP];
__device__ __half g_WqkvT[3*DM*DM];
__device__ __half g_WoT  [DM*DM];
__device__ __half g_WinT [DMLP*DM];
__device__ __half g_WoutT[DM*DMLP];
__device__ float  g_qkvb[3*DM];

typedef unsigned long long u64;

// gelu with hardware tanh approximation (MUFU, single op)
__device__ __forceinline__ float gelu_new(float x) {
    float x3 = x * x * x;
    float a  = 0.7978845608028654f * (x + 0.044715f * x3);
    float t;
    asm("tanh.approx.f32 %0, %1;" : "=f"(t) : "f"(a));
    return 0.5f * x * (1.0f + t);
}

// ---------------- mma / ldmatrix / cp.async helpers ----------------------------
__device__ __forceinline__ uint32_t smem_u32(const void* p) {
    uint32_t a;
    asm("{ .reg .u64 t; cvta.to.shared.u64 t, %1; cvt.u32.u64 %0, t; }" : "=r"(a) : "l"(p));
    return a;
}
__device__ __forceinline__ void cpasync16(uint32_t dst, const void* src) {
    asm volatile("cp.async.cg.shared.global [%0], [%1], 16;" :: "r"(dst), "l"(src));
}
#define CP_COMMIT() asm volatile("cp.async.commit_group;" ::: "memory")
#define CP_WAIT1()  asm volatile("cp.async.wait_group 1;" ::: "memory")
#define CP_WAIT0()  asm volatile("cp.async.wait_group 0;" ::: "memory")

__device__ __forceinline__ void ldsm4(uint32_t &r0, uint32_t &r1, uint32_t &r2, uint32_t &r3,
                                      uint32_t addr) {
    asm volatile("ldmatrix.sync.aligned.m8n8.x4.shared.b16 {%0,%1,%2,%3}, [%4];"
                 : "=r"(r0), "=r"(r1), "=r"(r2), "=r"(r3) : "r"(addr));
}
__device__ __forceinline__ void ldsm4t(uint32_t &r0, uint32_t &r1, uint32_t &r2, uint32_t &r3,
                                       uint32_t addr) {
    asm volatile("ldmatrix.sync.aligned.m8n8.x4.trans.shared.b16 {%0,%1,%2,%3}, [%4];"
                 : "=r"(r0), "=r"(r1), "=r"(r2), "=r"(r3) : "r"(addr));
}
__device__ __forceinline__ void mma16816(float* c, uint32_t a0, uint32_t a1, uint32_t a2,
                                         uint32_t a3, uint32_t b0, uint32_t b1) {
    asm volatile("mma.sync.aligned.m16n8k16.row.col.f32.f16.f16.f32 "
                 "{%0,%1,%2,%3},{%4,%5,%6,%7},{%8,%9},{%0,%1,%2,%3};"
                 : "+f"(c[0]), "+f"(c[1]), "+f"(c[2]), "+f"(c[3])
                 : "r"(a0), "r"(a1), "r"(a2), "r"(a3), "r"(b0), "r"(b1));
}
__device__ __forceinline__ uint32_t exp2_h2(float e0, float e1) {
    __half2 h = __floats2half2_rn(e0, e1);
    uint32_t hi = *(uint32_t*)&h, r;
    asm("ex2.approx.f16x2 %0, %1;" : "=r"(r) : "r"(hi));
    return r;
}
__device__ __forceinline__ float exp2_poly(float t) {
    t = fmaxf(t, -30.0f);
    const float z = t + 12582912.0f;
    const int   n = __float_as_int(z) << 23;
    const float f = t - (z - 12582912.0f);
    float p = 0.009618129f;
    p = fmaf(p, f, 0.05550411f);
    p = fmaf(p, f, 0.24022651f);
    p = fmaf(p, f, 0.69314718f);
    p = fmaf(p, f, 1.0f);
    return __int_as_float(__float_as_int(p) + n);
}

// ---------------- HMMA GEMM: BK=64, 3 stages, 8 warps, warp tile 64x32 ----------
// KT template = K/64 (compile-time trip count; KT % 3 == 0)
#define LDSH 72
#define STG_H (2 * 128 * LDSH)
#define GEMM_SMEM (3 * STG_H * 2)        // 110592 B

template<int EPI, int KT>
__global__ void __launch_bounds__(256, 2) mma_gemm(
    const __half* __restrict__ A, const __half* __restrict__ Bt,
    const float* __restrict__ bias, const float* __restrict__ R,
    float* __restrict__ C, __half* __restrict__ Ch,
    __half* __restrict__ Qp, __half* __restrict__ Kp, __half* __restrict__ Vp,
    int N)
{
    constexpr int K = KT * 64;
    extern __shared__ __half sm[];
    const int tid  = threadIdx.x;
    const int lane = tid & 31, wid = tid >> 5;
    const int wm = wid >> 2, wn = wid & 3;
    const int col0 = blockIdx.x * 128;
    const int row0 = blockIdx.y * 128;

    const uint32_t sbase = smem_u32(sm);

    float acc[4][4][4];
    #pragma unroll
    for (int i = 0; i < 4; i++)
        #pragma unroll
        for (int j = 0; j < 4; j++)
            #pragma unroll
            for (int x = 0; x < 4; x++) acc[i][j][x] = 0.0f;

    auto load_stage = [&](uint32_t st, int kt) {
        const int kk = kt * 64;
        #pragma unroll
        for (int h = 0; h < 4; h++) {
            const int c  = tid + h * 256;
            const int r  = c >> 3;
            const int kc = (c & 7) * 8;
            cpasync16(st + (uint32_t)(r * LDSH + kc) * 2,
                      A + (size_t)(row0 + r) * K + kk + kc);
            cpasync16(st + (uint32_t)((128 + r) * LDSH + kc) * 2,
                      Bt + (size_t)(col0 + r) * K + kk + kc);
        }
    };

    auto compute_stage = [&](uint32_t aB) {
        const uint32_t bB = aB + 128 * LDSH * 2;
        const int lrow = lane & 15;
        const int lcol = (lane >> 4) * 8;
        #pragma unroll
        for (int ks = 0; ks < 4; ks++) {
            const int ko = ks * 16 + lcol;
            uint32_t af[4][4];
            #pragma unroll
            for (int i = 0; i < 4; i++) {
                const int row = wm * 64 + i * 16 + lrow;
                ldsm4(af[i][0], af[i][1], af[i][2], af[i][3],
                      aB + (uint32_t)(row * LDSH + ko) * 2);
            }
            uint32_t bf[2][4];
            #pragma unroll
            for (int j = 0; j < 2; j++) {
                const int row = wn * 32 + j * 16 + lrow;
                ldsm4(bf[j][0], bf[j][1], bf[j][2], bf[j][3],
                      bB + (uint32_t)(row * LDSH + ko) * 2);
            }
            #pragma unroll
            for (int i = 0; i < 4; i++)
                #pragma unroll
                for (int j = 0; j < 4; j++)
                    mma16816(acc[i][j], af[i][0], af[i][1], af[i][2], af[i][3],
                             bf[j >> 1][j & 1], bf[j >> 1][(j & 1) + 2]);
        }
    };

    const uint32_t st0 = sbase;
    const uint32_t st1 = sbase + (STG_H * 2);
    const uint32_t st2 = sbase + 2 * (STG_H * 2);

    load_stage(st0, 0); CP_COMMIT();
    load_stage(st1, 1); CP_COMMIT();

    static_assert(KT % 3 == 0, "KT must be a multiple of 3");
    #pragma unroll 1
    for (int kt = 0; kt < KT; kt += 3) {
        // stage 0
        CP_WAIT1();
        __syncthreads();
        if (kt + 2 < KT) load_stage(st2, kt + 2);
        CP_COMMIT();
        compute_stage(st0);
        // stage 1
        CP_WAIT1();
        __syncthreads();
        if (kt + 3 < KT) load_stage(st0, kt + 3);
        CP_COMMIT();
        compute_stage(st1);
        // stage 2
        CP_WAIT1();
        __syncthreads();
        if (kt + 4 < KT) load_stage(st1, kt + 4);
        CP_COMMIT();
        compute_stage(st2);
    }

    const int g = lane >> 2, t4 = lane & 3;
    #pragma unroll
    for (int i = 0; i < 4; i++) {
        const int r0g = row0 + wm * 64 + i * 16 + g;
        #pragma unroll
        for (int j = 0; j < 4; j++) {
            const int c0g = col0 + wn * 32 + j * 8 + t4 * 2;
            const float2 bb = *(const float2*)&bias[c0g];
            float* a = acc[i][j];
            if (EPI == 0) {
                float2 rA = *(const float2*)&R[(size_t)r0g * N + c0g];
                float2 rB = *(const float2*)&R[(size_t)(r0g + 8) * N + c0g];
                *(float2*)&C[(size_t)r0g * N + c0g] =
                    make_float2(a[0] + bb.x + rA.x, a[1] + bb.y + rA.y);
                *(float2*)&C[(size_t)(r0g + 8) * N + c0g] =
                    make_float2(a[2] + bb.x + rB.x, a[3] + bb.y + rB.y);
            } else if (EPI == 1) {
                *(__half2*)&Ch[(size_t)r0g * N + c0g] =
                    __floats2half2_rn(gelu_new(a[0] + bb.x), gelu_new(a[1] + bb.y));
                *(__half2*)&Ch[(size_t)(r0g + 8) * N + c0g] =
                    __floats2half2_rn(gelu_new(a[2] + bb.x), gelu_new(a[3] + bb.y));
            } else {
                const int which = c0g / DM;
                const int h2    = (c0g % DM) >> 6;
                const int e0    = c0g & 63;
                const float sc  = (which == 0) ? 0.125f : 1.0f;
                __half* OP = (which == 0) ? Qp : ((which == 1) ? Kp : Vp);
                __half* p0 = OP + ((size_t)((r0g >> 10) * NH + h2)) * (SEQ * DH)
                               + (size_t)(r0g & (SEQ - 1)) * DH + e0;
                __half* p1 = OP + ((size_t)(((r0g + 8) >> 10) * NH + h2)) * (SEQ * DH)
                               + (size_t)((r0g + 8) & (SEQ - 1)) * DH + e0;
                *(__half2*)p0 = __floats2half2_rn((a[0] + bb.x) * sc, (a[1] + bb.y) * sc);
                *(__half2*)p1 = __floats2half2_rn((a[2] + bb.x) * sc, (a[3] + bb.y) * sc);
            }
        }
    }
}

// ---------------- merged prep + LN1 (one launch) --------------------------------
__device__ __forceinline__ void tr_tile(const float* __restrict__ in,
                                        __half* __restrict__ out,
                                        int C, int ldo, int c0, int r0,
                                        float* t, int tx, int ty)
{
    #pragma unroll
    for (int i = 0; i < 32; i += 8)
        t[(ty + i) * 33 + tx] = in[(size_t)(r0 + ty + i) * C + c0 + tx];
    __syncthreads();
    #pragma unroll
    for (int i = 0; i < 32; i += 8)
        out[(size_t)(c0 + ty + i) * ldo + r0 + tx] = __float2half(t[tx * 33 + ty + i]);
}

__device__ __forceinline__ void ln_row(const float* __restrict__ w,
                                       const float* __restrict__ b,
                                       __half* __restrict__ y, int t,
                                       float v0, float v1, float v2, float* sh)
{
    float s = v0 + v1 + v2;
    float q = v0 * v0 + v1 * v1 + v2 * v2;
    #pragma unroll
    for (int o = 16; o > 0; o >>= 1) {
        s += __shfl_xor_sync(0xffffffffu, s, o);
        q += __shfl_xor_sync(0xffffffffu, q, o);
    }
    const int lane = t & 31, wid = t >> 5;
    if (lane == 0) { sh[wid] = s; sh[wid + 8] = q; }
    __syncthreads();
    if (t == 0) {
        float ss = 0.f, qq = 0.f;
        #pragma unroll
        for (int i = 0; i < 8; i++) { ss += sh[i]; qq += sh[i + 8]; }
        sh[0] = ss; sh[8] = qq;
    }
    __syncthreads();
    s = sh[0]; q = sh[8];
    const float mu  = s * (1.0f / DM);
    const float inv = rsqrtf(q * (1.0f / DM) - mu * mu + 1e-5f);
    y[t]       = __float2half((v0 - mu) * inv * w[t]       + b[t]);
    y[t + 256] = __float2half((v1 - mu) * inv * w[t + 256] + b[t + 256]);
    y[t + 512] = __float2half((v2 - mu) * inv * w[t + 512] + b[t + 512]);
}

__global__ void __launch_bounds__(256) prep_ln1(
    const float* __restrict__ WQ, const float* __restrict__ WK, const float* __restrict__ WV,
    const float* __restrict__ WO, const float* __restrict__ Win, const float* __restrict__ Wout,
    const float* __restrict__ bq, const float* __restrict__ bk, const float* __restrict__ bv,
    __half* __restrict__ WqkvT, __half* __restrict__ WoT,
    __half* __restrict__ WinT,  __half* __restrict__ WoutT,
    float* __restrict__ qkvb,
    const float* __restrict__ X, const float* __restrict__ ln1w,
    const float* __restrict__ ln1b, __half* __restrict__ n1h)
{
    __shared__ float t[32 * 33];
    const int bid = blockIdx.x;
    const int tid = threadIdx.x;
    const int tx = tid & 31, ty = tid >> 5;

    if (bid < 1728) {
        const int which = bid / 576;
        const int r = bid % 576;
        const int h = r / 48, u = r % 48;
        const int c0 = (u & 1) * 32, r0 = (u >> 1) * 32;
        const float* in = ((which == 0) ? WQ : (which == 1) ? WK : WV) + (size_t)h * DM * DH;
        __half* out = WqkvT + (size_t)which * DM * DM + (size_t)h * DH * DM;
        tr_tile(in, out, DH, DM, c0, r0, t, tx, ty);
    } else if (bid < 2304) {
        const int r = bid - 1728;
        const int h = r / 48, u = r % 48;
        const int c0 = (u % 24) * 32, r0 = (u / 24) * 32;
        tr_tile(WO + (size_t)h * DH * DM, WoT + h * DH, DM, DM, c0, r0, t, tx, ty);
    } else if (bid < 4608) {
        const int r = bid - 2304;
        const int c0 = (r % 96) * 32, r0 = (r / 96) * 32;
        tr_tile(Win, WinT, DMLP, DM, c0, r0, t, tx, ty);
    } else if (bid < 6912) {
        const int r = bid - 4608;
        const int c0 = (r % 24) * 32, r0 = (r / 24) * 32;
        tr_tile(Wout, WoutT, DM, DMLP, c0, r0, t, tx, ty);
    } else if (bid < 6921) {
        const int n = (bid - 6912) * 256 + tid;
        if (n < 3 * DM) {
            const float* s = (n < DM) ? bq : ((n < 2 * DM) ? bk : bv);
            qkvb[n] = s[n % DM];
        }
    } else {
        const int row = bid - 6921;
        const float* x = X + (size_t)row * DM;
        ln_row(ln1w, ln1b, n1h + (size_t)row * DM, tid,
               x[tid], x[tid + 256], x[tid + 512], t);
    }
}

// ---------------- LayerNorm (fp32 in -> fp16 out), LN2 ---------------------------
__global__ void __launch_bounds__(256) ln_kernel(
    const float* __restrict__ X, const float* __restrict__ w,
    const float* __restrict__ b, __half* __restrict__ Y)
{
    __shared__ float sh[16];
    const int row = blockIdx.x;
    const float* x = X + (size_t)row * DM;
    const int t = threadIdx.x;
    ln_row(w, b, Y + (size_t)row * DM, t, x[t], x[t + 256], x[t + 512], sh);
}

// ---------------- tensor-core causal flash attention (round-5 best) -------------
#define ALD 72
#define ATTN_SMEM ((64 + 128 + 128) * ALD * 2)
#define L2E 1.4426950408889634f

__global__ void __launch_bounds__(128) attn_mma(
    const __half* __restrict__ Q, const __half* __restrict__ K,
    const __half* __restrict__ V, __half* __restrict__ Z)
{
    extern __shared__ __half as_[];
    __half* Qs = as_;
    __half* Ks = as_ + 64 * ALD;
    __half* Vs = as_ + (64 + 128) * ALD;

    const int tid  = threadIdx.x;
    const int lane = tid & 31;
    const int w    = tid >> 5;
    const int bh   = blockIdx.y;
    const int q0   = (15 - blockIdx.x) * 64;
    const int nt   = q0 / 64 + 1;

    const __half* Qb = Q + (size_t)bh * (SEQ * DH);
    const __half* Kb = K + (size_t)bh * (SEQ * DH);
    const __half* Vb = V + (size_t)bh * (SEQ * DH);

    const uint32_t sQ = smem_u32(Qs);
    const uint32_t sK = smem_u32(Ks);
    const uint32_t sV = smem_u32(Vs);

    #pragma unroll
    for (int i = 0; i < 4; i++) {
        int c = tid + i * 128;
        int row = c >> 3, col = (c & 7) * 8;
        *(float4*)&Qs[row * ALD + col] = *(const float4*)&Qb[(size_t)(q0 + row) * DH + col];
    }

    auto load_kv = [&](int kt, int buf) {
        const int k0 = kt * 64;
        const uint32_t bK_ = sK + (uint32_t)buf * (64 * ALD * 2);
        const uint32_t bV_ = sV + (uint32_t)buf * (64 * ALD * 2);
        #pragma unroll
        for (int i = 0; i < 4; i++) {
            int c = tid + i * 128;
            int row = c >> 3, col = (c & 7) * 8;
            cpasync16(bK_ + (uint32_t)(row * ALD + col) * 2,
                      Kb + (size_t)(k0 + row) * DH + col);
            cpasync16(bV_ + (uint32_t)(row * ALD + col) * 2,
                      Vb + (size_t)(k0 + row) * DH + col);
        }
    };

    load_kv(0, 0); CP_COMMIT();
    __syncthreads();

    uint32_t qf[4][4];
    {
        const uint32_t qoff = sQ + (uint32_t)((w * 16 + (lane & 15)) * ALD + (lane >> 4) * 8) * 2;
        #pragma unroll
        for (int ks = 0; ks < 4; ks++)
            ldsm4(qf[ks][0], qf[ks][1], qf[ks][2], qf[ks][3], qoff + ks * 32);
    }

    float o[8][4];
    #pragma unroll
    for (int j = 0; j < 8; j++)
        #pragma unroll
        for (int x = 0; x < 4; x++) o[j][x] = 0.0f;
    float m0 = -1e30f, m1 = -1e30f, l0 = 0.0f, l1 = 0.0f;

    const uint32_t koff = (uint32_t)(((lane >> 4) * 8 + (lane & 7)) * ALD + ((lane >> 3) & 1) * 8) * 2;
    const uint32_t voff = (uint32_t)(((lane & 7) + ((lane >> 3) & 1) * 8) * ALD + (lane >> 4) * 8) * 2;
    const int grow = lane >> 2, gcol = (lane & 3) * 2;

    for (int kt = 0; kt < nt; kt++) {
        const int buf = kt & 1;
        if (kt + 1 < nt) { load_kv(kt + 1, buf ^ 1); CP_COMMIT(); CP_WAIT1(); }
        else            { CP_WAIT0(); }
        __syncthreads();

        const uint32_t bK_ = sK + (uint32_t)buf * (64 * ALD * 2);
        const uint32_t bV_ = sV + (uint32_t)buf * (64 * ALD * 2);

        float c_[8][4];
        #pragma unroll
        for (int j = 0; j < 8; j++)
            #pragma unroll
            for (int x = 0; x < 4; x++) c_[j][x] = 0.0f;
        #pragma unroll
        for (int ks = 0; ks < 4; ks++) {
            #pragma unroll
            for (int j2 = 0; j2 < 4; j2++) {
                uint32_t b0, b1, b2, b3;
                ldsm4(b0, b1, b2, b3, bK_ + koff + (uint32_t)(j2 * 16 * ALD + ks * 16) * 2);
                mma16816(c_[2 * j2],     qf[ks][0], qf[ks][1], qf[ks][2], qf[ks][3], b0, b1);
                mma16816(c_[2 * j2 + 1], qf[ks][0], qf[ks][1], qf[ks][2], qf[ks][3], b2, b3);
            }
        }

        if (kt == nt - 1) {
            const int row0 = q0 + w * 16 + grow;
            const int k0   = kt * 64;
            #pragma unroll
            for (int j = 0; j < 8; j++) {
                const int col = k0 + j * 8 + gcol;
                if (col     > row0)     c_[j][0] = -1e30f;
                if (col + 1 > row0)     c_[j][1] = -1e30f;
                if (col     > row0 + 8) c_[j][2] = -1e30f;
                if (col + 1 > row0 + 8) c_[j][3] = -1e30f;
            }
        }

        float tm0 = -1e30f, tm1 = -1e30f;
        #pragma unroll
        for (int j = 0; j < 8; j++) {
            tm0 = fmaxf(tm0, fmaxf(c_[j][0], c_[j][1]));
            tm1 = fmaxf(tm1, fmaxf(c_[j][2], c_[j][3]));
        }
        tm0 = fmaxf(tm0, __shfl_xor_sync(0xffffffffu, tm0, 1));
        tm0 = fmaxf(tm0, __shfl_xor_sync(0xffffffffu, tm0, 2));
        tm1 = fmaxf(tm1, __shfl_xor_sync(0xffffffffu, tm1, 1));
        tm1 = fmaxf(tm1, __shfl_xor_sync(0xffffffffu, tm1, 2));
        const float mn0 = fmaxf(m0, tm0), mn1 = fmaxf(m1, tm1);
        const float corr0 = exp2_poly((m0 - mn0) * L2E);
        const float corr1 = exp2_poly((m1 - mn1) * L2E);
        m0 = mn0; m1 = mn1;

        uint32_t ph[8][2];
        float s0 = 0.0f, s1 = 0.0f;
        #pragma unroll
        for (int j = 0; j < 8; j++) {
            ph[j][0] = exp2_h2((c_[j][0] - mn0) * L2E, (c_[j][1] - mn0) * L2E);
            float2 p0 = __half22float2(*(__half2*)&ph[j][0]);
            s0 += p0.x + p0.y;
            const float e2 = exp2_poly((c_[j][2] - mn1) * L2E);
            const float e3 = exp2_poly((c_[j][3] - mn1) * L2E);
            __half2 hh2 = __floats2half2_rn(e2, e3);
            ph[j][1] = *(uint32_t*)&hh2;
            s1 += e2 + e3;
        }
        s0 += __shfl_xor_sync(0xffffffffu, s0, 1);
        s0 += __shfl_xor_sync(0xffffffffu, s0, 2);
        s1 += __shfl_xor_sync(0xffffffffu, s1, 1);
        s1 += __shfl_xor_sync(0xffffffffu, s1, 2);
        l0 = l0 * corr0 + s0;
        l1 = l1 * corr1 + s1;
        #pragma unroll
        for (int j = 0; j < 8; j++) {
            o[j][0] *= corr0; o[j][1] *= corr0;
            o[j][2] *= corr1; o[j][3] *= corr1;
        }

        #pragma unroll
        for (int ks = 0; ks < 4; ks++) {
            const uint32_t a0 = ph[2 * ks][0],     a1 = ph[2 * ks][1];
            const uint32_t a2 = ph[2 * ks + 1][0], a3 = ph[2 * ks + 1][1];
            #pragma unroll
            for (int j2 = 0; j2 < 4; j2++) {
                uint32_t b0, b1, b2, b3;
                ldsm4t(b0, b1, b2, b3, bV_ + voff + (uint32_t)(ks * 16 * ALD + j2 * 16) * 2);
                mma16816(o[2 * j2],     a0, a1, a2, a3, b0, b1);
                mma16816(o[2 * j2 + 1], a0, a1, a2, a3, b2, b3);
            }
        }
        __syncthreads();
    }

    const int b = bh / NH, h = bh % NH;
    const float i0 = __fdividef(1.0f, l0), i1 = __fdividef(1.0f, l1);
    const int row0 = q0 + w * 16 + grow;
    const size_t t0 = (size_t)b * SEQ + row0;
    const size_t t1 = t0 + 8;
    #pragma unroll
    for (int j = 0; j < 8; j++) {
        const int col = h * DH + j * 8 + gcol;
        *(__half2*)&Z[t0 * DM + col] = __floats2half2_rn(o[j][0] * i0, o[j][1] * i0);
        *(__half2*)&Z[t1 * DM + col] = __floats2half2_rn(o[j][2] * i1, o[j][3] * i1);
    }
}

// ---------------- launch --------------------------------------------------------
extern "C" void kernel_launch(void* const* d_in, const int* in_sizes, int n_in,
                              void* d_out, int out_size) {
    const float* resid_pre = (const float*)d_in[0];
    const float* W_Q  = (const float*)d_in[1];
    const float* b_Q  = (const float*)d_in[2];
    const float* W_K  = (const float*)d_in[3];
    const float* b_K  = (const float*)d_in[4];
    const float* W_V  = (const float*)d_in[5];
    const float* b_V  = (const float*)d_in[6];
    const float* W_O  = (const float*)d_in[7];
    const float* b_O  = (const float*)d_in[8];
    const float* ln1w = (const float*)d_in[9];
    const float* ln1b = (const float*)d_in[10];
    const float* ln2w = (const float*)d_in[11];
    const float* ln2b = (const float*)d_in[12];
    const float* W_in = (const float*)d_in[13];
    const float* b_in = (const float*)d_in[14];
    const float* W_out= (const float*)d_in[15];
    const float* b_out= (const float*)d_in[16];
    float* out = (float*)d_out;

    __half *n1h, *zh, *n2h, *hh, *WqkvT, *WoT, *WinT, *WoutT, *q, *k, *v;
    float *rm, *qkvb;
    cudaGetSymbolAddress((void**)&n1h,  g_n1h);
    cudaGetSymbolAddress((void**)&q,    g_q);
    cudaGetSymbolAddress((void**)&k,    g_k);
    cudaGetSymbolAddress((void**)&v,    g_v);
    cudaGetSymbolAddress((void**)&zh,   g_zh);
    cudaGetSymbolAddress((void**)&rm,   g_rm);
    cudaGetSymbolAddress((void**)&n2h,  g_n2h);
    cudaGetSymbolAddress((void**)&hh,   g_hh);
    cudaGetSymbolAddress((void**)&WqkvT,g_WqkvT);
    cudaGetSymbolAddress((void**)&WoT,  g_WoT);
    cudaGetSymbolAddress((void**)&WinT, g_WinT);
    cudaGetSymbolAddress((void**)&WoutT,g_WoutT);
    cudaGetSymbolAddress((void**)&qkvb, g_qkvb);

    cudaFuncSetAttribute((const void*)mma_gemm<0,12>, cudaFuncAttributeMaxDynamicSharedMemorySize, GEMM_SMEM);
    cudaFuncSetAttribute((const void*)mma_gemm<0,48>, cudaFuncAttributeMaxDynamicSharedMemorySize, GEMM_SMEM);
    cudaFuncSetAttribute((const void*)mma_gemm<1,12>, cudaFuncAttributeMaxDynamicSharedMemorySize, GEMM_SMEM);
    cudaFuncSetAttribute((const void*)mma_gemm<2,12>, cudaFuncAttributeMaxDynamicSharedMemorySize, GEMM_SMEM);
    cudaFuncSetAttribute((const void*)attn_mma,       cudaFuncAttributeMaxDynamicSharedMemorySize, ATTN_SMEM);

    prep_ln1<<<6921 + TOK, 256>>>(W_Q, W_K, W_V, W_O, W_in, W_out,
                                  b_Q, b_K, b_V,
                                  WqkvT, WoT, WinT, WoutT, qkvb,
                                  resid_pre, ln1w, ln1b, n1h);

    mma_gemm<2,12><<<dim3(18, 64), 256, GEMM_SMEM>>>(n1h, WqkvT, qkvb, nullptr,
                                                     nullptr, nullptr, q, k, v, 3*DM);
    attn_mma<<<dim3(16, 96), 128, ATTN_SMEM>>>(q, k, v, zh);
    mma_gemm<0,12><<<dim3(6, 64), 256, GEMM_SMEM>>>(zh, WoT, b_O, resid_pre,
                                                    rm, nullptr, nullptr, nullptr, nullptr, DM);
    ln_kernel<<<TOK, 256>>>(rm, ln2w, ln2b, n2h);
    mma_gemm<1,12><<<dim3(24, 64), 256, GEMM_SMEM>>>(n2h, WinT, b_in, nullptr,
                                                     nullptr, hh, nullptr, nullptr, nullptr, DMLP);
    mma_gemm<0,48><<<dim3(6, 64), 256, GEMM_SMEM>>>(hh, WoutT, b_out, rm,
                                                    out, nullptr, nullptr, nullptr, nullptr, DM);
}